// round 13
// baseline (speedup 1.0000x reference)
#include <cuda_runtime.h>
#include <cuda.h>
#include <cuda_bf16.h>

// CLSTM cell, persistent fused kernel, TMA edition (R8 GEMM + CONCURRENT prep):
//   init (tiny, stream 0): zero slab counters; combined bias.
//   prep (stream 2, forked via events): bf16 hi/lo split of X and sign-combined
//        N-interleaved weights, in 4 K-slabs of 1024, publishing g_cnt[s].
//   gemm (stream 0, concurrent with prep): 74 persistent 2-CTA clusters,
//        256x256 tiles, tcgen05 cg2 bf16 SS MMA, 3-stage TMA pipe, double-buffered
//        TMEM, fused LSTM epilogue. Tile-0 TMA chunks gate on g_cnt.

#define BDIM 4096
#define HDIM 1024
#define KTOT 4096
#define NTOT 8192
#define PREP_BLOCKS 1536
#define SLAB_TASKS 3145728u      // (4096 + 8192) rows x 256 float4 per 1024-K slab

__device__ __align__(256) __nv_bfloat16 g_Ah[(size_t)BDIM * KTOT];
__device__ __align__(256) __nv_bfloat16 g_Al[(size_t)BDIM * KTOT];
__device__ __align__(256) __nv_bfloat16 g_Bh[(size_t)NTOT * KTOT];
__device__ __align__(256) __nv_bfloat16 g_Bl[(size_t)NTOT * KTOT];
__device__ float g_biasC[NTOT];
__device__ unsigned g_cnt[4];
__device__ float g_z[(size_t)BDIM * NTOT];   // HMMA fallback only

__device__ __forceinline__ unsigned smem_to_u32(const void* p) {
    unsigned a;
    asm("{ .reg .u64 t; cvta.to.shared.u64 t, %1; cvt.u32.u64 %0, t; }"
        : "=r"(a) : "l"(p));
    return a;
}
__device__ __forceinline__ void cp_async16(unsigned dst, const void* src) {
    asm volatile("cp.async.cg.shared.global [%0], [%1], 16;"
        :: "r"(dst), "l"(src) : "memory");
}
#define CP_COMMIT() asm volatile("cp.async.commit_group;" ::: "memory")
#define CP_WAIT1()  asm volatile("cp.async.wait_group 1;" ::: "memory")

__device__ __forceinline__ float sigmoidf_(float x) {
    return 1.0f / (1.0f + expf(-x));
}
__device__ __forceinline__ void cell_math(const float zr0, const float zi0,
                                          const float zr1, const float zi1,
                                          const float zr2, const float zi2,
                                          const float zr3, const float zi3,
                                          const float cr, const float ci,
                                          float& htr, float& hti,
                                          float& ctr, float& cti) {
    const float fr = sigmoidf_(zr0), fi = sigmoidf_(zi0);
    const float ir = sigmoidf_(zr1), ii = sigmoidf_(zi1);
    const float ar = tanhf(zr2),     ai = tanhf(zi2);
    const float orr = sigmoidf_(zr3), oi = sigmoidf_(zi3);
    ctr = (cr * fr - ci * fi) + (ar * ir - ai * ii);
    cti = (cr * fi + ci * fr) + (ar * ii + ai * ir);
    const float tr = tanhf(ctr), ti = tanhf(cti);
    htr = orr * tr - oi * ti;
    hti = orr * ti + oi * tr;
}

__device__ __forceinline__ void gate_slab(unsigned sl) {
    unsigned v;
    while (true) {
        asm volatile("ld.acquire.gpu.global.u32 %0, [%1];"
            : "=r"(v) : "l"(&g_cnt[sl]) : "memory");
        if (v >= (unsigned)PREP_BLOCKS) break;
        __nanosleep(256);
    }
}

#define NSTAGE 3
#define SMEM_BYTES (4096 + NSTAGE * 65536)
#define NTILES_TOT 512
#define NCLUST 74

__global__ __launch_bounds__(256, 1) __cluster_dims__(2, 1, 1)
void clstm_tc_gemm_kernel(const float* __restrict__ c_x, float* __restrict__ out,
                          const __grid_constant__ CUtensorMap tmAh,
                          const __grid_constant__ CUtensorMap tmAl,
                          const __grid_constant__ CUtensorMap tmBh,
                          const __grid_constant__ CUtensorMap tmBl) {
    extern __shared__ __align__(1024) char dsm[];
    const unsigned rank = blockIdx.x & 1;
    const unsigned cid  = blockIdx.x >> 1;               // 0..73
    const unsigned ntiles = (NTILES_TOT - 1 - cid) / NCLUST + 1;
    const int tid = threadIdx.x;

#ifdef __CUDA_ARCH_FEAT_SM103_ALL
    #define KCH 64
    #define NCHUNK (KTOT / KCH)
    #define STAGE_BYTES 65536
    #define A_H 0
    #define A_L 16384
    #define B_H 32768
    #define B_L 49152
    #define IDESC ((1u << 4) | (1u << 7) | (1u << 10) | (16u << 17) | (16u << 24))
    #define CHUNK_TX 131072u     // 2 CTAs x 64KB

    const unsigned base = smem_to_u32(dsm);
    const unsigned empB  = base + 0;      // 3 x 8B
    const unsigned xfB   = base + 24;     // 3 x 8B (leader's: TMA complete_tx)
    const unsigned accdB = base + 48;     // 2 x 8B
    const unsigned accfB = base + 64;     // 2 x 8B
    const unsigned tptr  = base + 80;
    float* sbias = (float*)(dsm + 1024);  // [2][256]
    const unsigned tiles = base + 4096;

    #define MBAR_INIT(a, c) \
        asm volatile("mbarrier.init.shared.b64 [%0], %1;" :: "r"(a), "r"((unsigned)(c)) : "memory")
    #define MBAR_EXPECT_TX(a, bytes) \
        asm volatile("mbarrier.arrive.expect_tx.shared.b64 _, [%0], %1;" \
            :: "r"(a), "r"((unsigned)(bytes)) : "memory")
    #define MBAR_WAIT(a, ph) do {                                                   \
        asm volatile("{\n\t.reg .pred P1;\n\t"                                      \
            "WL_%=:\n\t"                                                            \
            "mbarrier.try_wait.parity.acquire.cta.shared::cta.b64 P1, [%0], %1, 0x989680;\n\t" \
            "@P1 bra.uni WD_%=;\n\t"                                                \
            "bra.uni WL_%=;\n\t"                                                    \
            "WD_%=:\n\t}"                                                           \
            :: "r"(a), "r"((unsigned)(ph)) : "memory");                             \
    } while (0)
    #define MBAR_WAIT_CL(a, ph) do {                                                \
        asm volatile("{\n\t.reg .pred P1;\n\t"                                      \
            "WL_%=:\n\t"                                                            \
            "mbarrier.try_wait.parity.acquire.cluster.shared::cta.b64 P1, [%0], %1, 0x989680;\n\t" \
            "@P1 bra.uni WD_%=;\n\t"                                                \
            "bra.uni WL_%=;\n\t"                                                    \
            "WD_%=:\n\t}"                                                           \
            :: "r"(a), "r"((unsigned)(ph)) : "memory");                             \
    } while (0)
    #define CLUSTER_SYNC_() do {                                                    \
        asm volatile("barrier.cluster.arrive.aligned;" ::: "memory");               \
        asm volatile("barrier.cluster.wait.aligned;" ::: "memory");                 \
    } while (0)
    #define MMA_CG2(d, adesc, bdesc, en) \
        asm volatile("{\n\t.reg .pred p;\n\tsetp.ne.u32 p, %4, 0;\n\t"              \
            "tcgen05.mma.cta_group::2.kind::f16 [%0], %1, %2, %3, "                 \
            "{%5,%5,%5,%5,%5,%5,%5,%5}, p;\n\t}"                                    \
            :: "r"(d), "l"(adesc), "l"(bdesc), "r"(IDESC), "r"((unsigned)(en)),     \
               "r"(0u) : "memory")
    #define TMA2D_CG2(dst, map, cx, cy, mbar) \
        asm volatile("{\n\t.reg .b32 lb;\n\t"                                       \
            "and.b32 lb, %4, 0xFEFFFFFF;\n\t"                                       \
            "cp.async.bulk.tensor.2d.cta_group::2.shared::cluster.global"           \
            ".tile.mbarrier::complete_tx::bytes [%0], [%1, {%2, %3}], [lb];\n\t}"   \
            :: "r"(dst), "l"(map), "r"((int)(cx)), "r"((int)(cy)), "r"(mbar)        \
            : "memory")

    if (tid == 0) {
#pragma unroll
        for (int s = 0; s < NSTAGE; s++) {
            MBAR_INIT(empB + s * 8, 1);
            MBAR_INIT(xfB  + s * 8, 1);
        }
        MBAR_INIT(accdB + 0, 1); MBAR_INIT(accdB + 8, 1);
        MBAR_INIT(accfB + 0, 2); MBAR_INIT(accfB + 8, 2);
    }
    if ((tid >> 5) == 4)
        asm volatile("tcgen05.alloc.cta_group::2.sync.aligned.shared::cta.b32 [%0], %1;"
            :: "r"(tptr), "r"(512u) : "memory");
    __syncthreads();

    unsigned tmem;
    asm volatile("ld.shared.b32 %0, [%1];" : "=r"(tmem) : "r"(tptr));

    if (rank == 0 && tid == 192) {
#pragma unroll
        for (int s = 0; s < NSTAGE; s++) MBAR_EXPECT_TX(xfB + s * 8, CHUNK_TX);
    }
    CLUSTER_SYNC_();

    if (tid < 128) {
        // ============ readback + fused LSTM epilogue (warps 0-3) ============
        const int lid = tid & 31;
        const unsigned woff = ((unsigned)(tid >> 5)) << 21;
        for (unsigned ti = 0; ti < ntiles; ti++) {
            const unsigned tile = ti * NCLUST + cid;
            const unsigned m0 = (tile >> 5) * 256;
            const unsigned n0 = (tile & 31) * 256;
            const unsigned b = ti & 1, u = ti >> 1;

            sbias[b * 256 + tid]       = g_biasC[n0 + tid];
            sbias[b * 256 + tid + 128] = g_biasC[n0 + tid + 128];

            MBAR_WAIT(accdB + b * 8, u & 1);
            asm volatile("tcgen05.fence::after_thread_sync;" ::: "memory");
            asm volatile("bar.sync 1, 128;" ::: "memory");

            const unsigned m = m0 + rank * 128 + (tid >> 5) * 32 + lid;
            const unsigned ob = n0 >> 3;
            const float* cxp = c_x + (size_t)m * 2048;
            const size_t hrow = (size_t)m * 2048;
            const size_t coff = (size_t)BDIM * 2048;
            const unsigned tb = tmem + b * 256 + woff;
#pragma unroll
            for (int j = 0; j < 8; j++) {
                unsigned r[32];
                asm volatile("tcgen05.ld.sync.aligned.32x32b.x32.b32 "
                    "{%0, %1, %2, %3, %4, %5, %6, %7, "
                    " %8, %9, %10, %11, %12, %13, %14, %15, "
                    " %16, %17, %18, %19, %20, %21, %22, %23, "
                    " %24, %25, %26, %27, %28, %29, %30, %31}, [%32];"
                    : "=r"(r[0]),  "=r"(r[1]),  "=r"(r[2]),  "=r"(r[3]),
                      "=r"(r[4]),  "=r"(r[5]),  "=r"(r[6]),  "=r"(r[7]),
                      "=r"(r[8]),  "=r"(r[9]),  "=r"(r[10]), "=r"(r[11]),
                      "=r"(r[12]), "=r"(r[13]), "=r"(r[14]), "=r"(r[15]),
                      "=r"(r[16]), "=r"(r[17]), "=r"(r[18]), "=r"(r[19]),
                      "=r"(r[20]), "=r"(r[21]), "=r"(r[22]), "=r"(r[23]),
                      "=r"(r[24]), "=r"(r[25]), "=r"(r[26]), "=r"(r[27]),
                      "=r"(r[28]), "=r"(r[29]), "=r"(r[30]), "=r"(r[31])
                    : "r"(tb + j * 32));
                asm volatile("tcgen05.wait::ld.sync.aligned;" ::: "memory");

                const unsigned o4 = ob + j * 4;
                const float4 cr4 = *reinterpret_cast<const float4*>(cxp + o4);
                const float4 ci4 = *reinterpret_cast<const float4*>(cxp + 1024 + o4);
                float htr[4], hti[4], ctr[4], cti[4];
#pragma unroll
                for (int q = 0; q < 4; q++) {
                    const int c0 = q * 8;
                    const float* sbp = sbias + b * 256 + j * 32 + c0;
                    cell_math(
                        __uint_as_float(r[c0 + 0]) + sbp[0], __uint_as_float(r[c0 + 1]) + sbp[1],
                        __uint_as_float(r[c0 + 2]) + sbp[2], __uint_as_float(r[c0 + 3]) + sbp[3],
                        __uint_as_float(r[c0 + 4]) + sbp[4], __uint_as_float(r[c0 + 5]) + sbp[5],
                        __uint_as_float(r[c0 + 6]) + sbp[6], __uint_as_float(r[c0 + 7]) + sbp[7],
                        (&cr4.x)[q], (&ci4.x)[q],
                        htr[q], hti[q], ctr[q], cti[q]);
                }
                *reinterpret_cast<float4*>(out + hrow + o4) =
                    make_float4(htr[0], htr[1], htr[2], htr[3]);
                *reinterpret_cast<float4*>(out + hrow + 1024 + o4) =
                    make_float4(hti[0], hti[1], hti[2], hti[3]);
                *reinterpret_cast<float4*>(out + coff + hrow + o4) =
                    make_float4(ctr[0], ctr[1], ctr[2], ctr[3]);
                *reinterpret_cast<float4*>(out + coff + hrow + 1024 + o4) =
                    make_float4(cti[0], cti[1], cti[2], cti[3]);
            }
            asm volatile("tcgen05.fence::before_thread_sync;" ::: "memory");
            asm volatile("bar.sync 1, 128;" ::: "memory");
            if (tid == 0) {
                asm volatile("{\n\t.reg .b32 rem;\n\t"
                    "mapa.shared::cluster.u32 rem, %0, 0;\n\t"
                    "mbarrier.arrive.release.cluster.shared::cluster.b64 _, [rem];\n\t}"
                    :: "r"(accfB + b * 8) : "memory");
            }
        }
    } else if (tid == 128) {
        // ============ TMA issuer (both CTAs), 6 loads/chunk; tile-0 gated ============
        unsigned ci = 0;
        for (unsigned ti = 0; ti < ntiles; ti++) {
            const unsigned tile = ti * NCLUST + cid;
            const unsigned m0 = (tile >> 5) * 256;
            const unsigned n0 = (tile & 31) * 256;
            const int yA  = (int)(m0 + rank * 128);
            const int yB0 = (int)(n0 + rank * 64);
            const int yB1 = (int)(n0 + 128 + rank * 64);
            for (int i = 0; i < NCHUNK; i++, ci++) {
                const unsigned s = ci % NSTAGE, w = ci / NSTAGE;
                if (w >= 1) MBAR_WAIT(empB + s * 8, (w - 1) & 1);
                if (ti == 0) {
                    gate_slab((unsigned)i >> 4);
                    asm volatile("fence.proxy.async;" ::: "memory");
                }
                const unsigned sb = tiles + s * STAGE_BYTES;
                const int k0 = i * KCH;
                const unsigned mb = xfB + s * 8;
                TMA2D_CG2(sb + A_H,        &tmAh, k0, yA,  mb);
                TMA2D_CG2(sb + A_L,        &tmAl, k0, yA,  mb);
                TMA2D_CG2(sb + B_H,        &tmBh, k0, yB0, mb);
                TMA2D_CG2(sb + B_H + 8192, &tmBh, k0, yB1, mb);
                TMA2D_CG2(sb + B_L,        &tmBl, k0, yB0, mb);
                TMA2D_CG2(sb + B_L + 8192, &tmBl, k0, yB1, mb);
            }
        }
    } else if (tid == 192 && rank == 0) {
        // ============ MMA issue thread (leader only) ============
        const unsigned long long DBASE =
            (2ull << 61) | (1ull << 46) | (64ull << 32) | (1ull << 16);
        unsigned ci = 0;
        for (unsigned ti = 0; ti < ntiles; ti++) {
            const unsigned b = ti & 1;
            if (ti >= 2) MBAR_WAIT_CL(accfB + b * 8, ((ti - 2) >> 1) & 1);
            const unsigned dbase = tmem + b * 256;
            for (int i = 0; i < NCHUNK; i++, ci++) {
                const unsigned s = ci % NSTAGE, w = ci / NSTAGE;
                MBAR_WAIT_CL(xfB + s * 8, w & 1);
                MBAR_EXPECT_TX(xfB + s * 8, CHUNK_TX);
                const unsigned sb = tiles + s * STAGE_BYTES;
                const unsigned long long ah = DBASE | ((unsigned long long)((sb + A_H) >> 4) & 0x3FFF);
                const unsigned long long al = DBASE | ((unsigned long long)((sb + A_L) >> 4) & 0x3FFF);
                const unsigned long long bh = DBASE | ((unsigned long long)((sb + B_H) >> 4) & 0x3FFF);
                const unsigned long long bl = DBASE | ((unsigned long long)((sb + B_L) >> 4) & 0x3FFF);
#pragma unroll
                for (int half = 0; half < 2; half++) {
                    const unsigned d = dbase + half * 128;
                    const unsigned long long bo = (unsigned long long)half * 512;
#pragma unroll
                    for (int ks = 0; ks < 4; ks++)
                        MMA_CG2(d, ah + ks * 2, bh + bo + ks * 2,
                                (i == 0 && ks == 0) ? 0u : 1u);
#pragma unroll
                    for (int ks = 0; ks < 4; ks++)
                        MMA_CG2(d, ah + ks * 2, bl + bo + ks * 2, 1u);
#pragma unroll
                    for (int ks = 0; ks < 4; ks++)
                        MMA_CG2(d, al + ks * 2, bh + bo + ks * 2, 1u);
                }
                asm volatile("tcgen05.commit.cta_group::2.mbarrier::arrive::one"
                    ".shared::cluster.multicast::cluster.b64 [%0], %1;"
                    :: "r"(empB + s * 8), "h"((unsigned short)0x3) : "memory");
            }
            asm volatile("tcgen05.commit.cta_group::2.mbarrier::arrive::one"
                ".shared::cluster.multicast::cluster.b64 [%0], %1;"
                :: "r"(accdB + b * 8), "h"((unsigned short)0x3) : "memory");
        }
    }
    __syncthreads();
    if ((tid >> 5) == 4) {
        asm volatile("tcgen05.relinquish_alloc_permit.cta_group::2.sync.aligned;");
        asm volatile("tcgen05.dealloc.cta_group::2.sync.aligned.b32 %0, %1;"
            :: "r"(tmem), "r"(512u));
    }
    CLUSTER_SYNC_();

#else
    // ======== HMMA fallback (plain sm_103; never selected on GB300) ========
    if (tid == 0) {
        for (unsigned sl = 0; sl < 4; sl++) gate_slab(sl);
    }
    __syncthreads();

    #define HKC 32
    #define HNCH (KTOT / HKC)
    #define HSTG 40960
    #define HA_H 0
    #define HA_L 10240
    #define HB_H 20480
    #define HB_L 30720
    #define RST 80

    const int lane = tid & 31;
    const int w = tid >> 5;
    const unsigned base = smem_to_u32(dsm);
    const unsigned m_base = (unsigned)(w & 1) * 64;
    const unsigned n_base = (unsigned)(w >> 1) * 32;

    #define LDSM_X4(r0, r1, r2, r3, addr) \
        asm volatile("ldmatrix.sync.aligned.m8n8.x4.shared.b16 {%0,%1,%2,%3}, [%4];" \
            : "=r"(r0), "=r"(r1), "=r"(r2), "=r"(r3) : "r"(addr))
    #define LDSM_X2(r0, r1, addr) \
        asm volatile("ldmatrix.sync.aligned.m8n8.x2.shared.b16 {%0,%1}, [%2];" \
            : "=r"(r0), "=r"(r1) : "r"(addr))
    #define MMA_BF16(ac, av, bv) \
        asm volatile("mma.sync.aligned.m16n8k16.row.col.f32.bf16.bf16.f32 " \
            "{%0,%1,%2,%3}, {%4,%5,%6,%7}, {%8,%9}, {%0,%1,%2,%3};" \
            : "+f"((ac)[0]), "+f"((ac)[1]), "+f"((ac)[2]), "+f"((ac)[3]) \
            : "r"((av)[0]), "r"((av)[1]), "r"((av)[2]), "r"((av)[3]), \
              "r"((bv)[0]), "r"((bv)[1]))

    for (unsigned ti = 0; ti < ntiles; ti++) {
        const unsigned tile = ti * NCLUST + cid;
        const unsigned m0 = (tile >> 5) * 256;
        const unsigned n0 = (tile & 31) * 256;
        const unsigned fm0 = m0 + rank * 128;

        for (int nh = 0; nh < 2; nh++) {
            const unsigned n0h = n0 + nh * 128;
            float acc[4][4][4];
#pragma unroll
            for (int a = 0; a < 4; a++)
#pragma unroll
                for (int bq = 0; bq < 4; bq++)
#pragma unroll
                    for (int c = 0; c < 4; c++) acc[a][bq][c] = 0.0f;

            auto load_stage = [&](unsigned sb, unsigned k0) {
                for (unsigned idx = (unsigned)tid; idx < 2048; idx += 256) {
                    const unsigned mat = idx >> 9;
                    const unsigned rem = idx & 511;
                    const unsigned row = rem >> 2;
                    const unsigned c = rem & 3;
                    const __nv_bfloat16* src;
                    if (mat == 0)      src = g_Ah + (size_t)(fm0 + row) * KTOT + k0 + c * 8;
                    else if (mat == 1) src = g_Al + (size_t)(fm0 + row) * KTOT + k0 + c * 8;
                    else if (mat == 2) src = g_Bh + (size_t)(n0h + row) * KTOT + k0 + c * 8;
                    else               src = g_Bl + (size_t)(n0h + row) * KTOT + k0 + c * 8;
                    cp_async16(sb + mat * 10240 + row * RST + c * 16, src);
                }
            };

            load_stage(base + 0 * HSTG, 0);   CP_COMMIT();
            load_stage(base + 1 * HSTG, HKC); CP_COMMIT();

            for (int i = 0; i < HNCH; i++) {
                CP_WAIT1();
                __syncthreads();
                if (i + 2 < HNCH) load_stage(base + (unsigned)((i + 2) % 3) * HSTG, (i + 2) * HKC);
                CP_COMMIT();

                const unsigned sb = base + (unsigned)(i % 3) * HSTG;
#pragma unroll
                for (int ks = 0; ks < 2; ks++) {
                    unsigned a[4][4], bhv[4][2], blv[4][2];
                    const unsigned acol = (unsigned)(ks * 2 + (lane >> 4)) * 16;
                    const unsigned bcol = (unsigned)(ks * 2 + ((lane >> 3) & 1)) * 16;
#pragma unroll
                    for (int mt = 0; mt < 4; mt++) {
                        const unsigned ad = sb + HA_H
                            + (m_base + mt * 16 + (lane & 15)) * RST + acol;
                        LDSM_X4(a[mt][0], a[mt][1], a[mt][2], a[mt][3], ad);
                    }
#pragma unroll
                    for (int nt = 0; nt < 4; nt++) {
                        const unsigned brow = (n_base + nt * 8 + (lane & 7)) * RST + bcol;
                        LDSM_X2(bhv[nt][0], bhv[nt][1], sb + HB_H + brow);
                        LDSM_X2(blv[nt][0], blv[nt][1], sb + HB_L + brow);
                    }
#pragma unroll
                    for (int mt = 0; mt < 4; mt++)
#pragma unroll
                        for (int nt = 0; nt < 4; nt++) {
                            MMA_BF16(acc[mt][nt], a[mt], bhv[nt]);
                            MMA_BF16(acc[mt][nt], a[mt], blv[nt]);
                        }
#pragma unroll
                    for (int mt = 0; mt < 4; mt++) {
                        const unsigned ad = sb + HA_L
                            + (m_base + mt * 16 + (lane & 15)) * RST + acol;
                        LDSM_X4(a[mt][0], a[mt][1], a[mt][2], a[mt][3], ad);
                    }
#pragma unroll
                    for (int mt = 0; mt < 4; mt++)
#pragma unroll
                        for (int nt = 0; nt < 4; nt++)
                            MMA_BF16(acc[mt][nt], a[mt], bhv[nt]);
                }
                __syncthreads();
            }

#pragma unroll
            for (int mt = 0; mt < 4; mt++) {
                const unsigned row0 = fm0 + m_base + mt * 16 + (lane >> 2);
#pragma unroll
                for (int nt = 0; nt < 4; nt++) {
                    const unsigned col = n0h + n_base + nt * 8 + 2 * (lane & 3);
                    *reinterpret_cast<float2*>(&g_z[(size_t)row0 * NTOT + col]) =
                        make_float2(acc[mt][nt][0], acc[mt][nt][1]);
                    *reinterpret_cast<float2*>(&g_z[(size_t)(row0 + 8) * NTOT + col]) =
                        make_float2(acc[mt][nt][2], acc[mt][nt][3]);
                }
            }
            __syncthreads();
        }

        for (int e = tid; e < 128 * 32; e += 256) {
            const unsigned rr = e >> 5, oq = e & 31;
            const unsigned m = fm0 + rr;
            const unsigned o = (n0 >> 3) + oq;
            const float* zp = g_z + (size_t)m * NTOT + n0 + oq * 8;
            const float* bp = g_biasC + n0 + oq * 8;
            const float cr = c_x[(size_t)m * 2048 + o];
            const float ci = c_x[(size_t)m * 2048 + 1024 + o];
            float htr, hti, ctr, cti;
            cell_math(zp[0] + bp[0], zp[1] + bp[1], zp[2] + bp[2], zp[3] + bp[3],
                      zp[4] + bp[4], zp[5] + bp[5], zp[6] + bp[6], zp[7] + bp[7],
                      cr, ci, htr, hti, ctr, cti);
            const size_t hrow = (size_t)m * 2048;
            const size_t coff = (size_t)BDIM * 2048;
            out[hrow + o] = htr;
            out[hrow + 1024 + o] = hti;
            out[coff + hrow + o] = ctr;
            out[coff + hrow + 1024 + o] = cti;
        }
        __syncthreads();
    }
#endif
}

// ---------------- slab-ordered prep kernel (concurrent stream) ----------------
__device__ __forceinline__ void split_bf16(float v, __nv_bfloat16& hi, __nv_bfloat16& lo) {
    hi = __float2bfloat16_rn(v);
    lo = __float2bfloat16_rn(v - __bfloat162float(hi));
}

__global__ __launch_bounds__(256)
void prep_slab_kernel(const float* __restrict__ input, const float* __restrict__ h_x,
                      const float* __restrict__ Uw_r, const float* __restrict__ Uw_i,
                      const float* __restrict__ Ww_r, const float* __restrict__ Ww_i) {
    for (unsigned s = 0; s < 4; s++) {
        for (unsigned t = blockIdx.x * 256u + threadIdx.x; t < SLAB_TASKS;
             t += (unsigned)PREP_BLOCKS * 256u) {
            const unsigned q = t & 255u;           // float4 within slab row
            const unsigned k = s * 1024u + q * 4u;
            if (t < 1048576u) {
                const unsigned m = t >> 8;
                const float* src = (k < 2048u) ? input + (size_t)m * 2048 + k
                                               : h_x   + (size_t)m * 2048 + (k - 2048u);
                float4 v = *reinterpret_cast<const float4*>(src);
                union { __nv_bfloat16 b[4]; uint2 u; } ph, pl;
                split_bf16(v.x, ph.b[0], pl.b[0]);
                split_bf16(v.y, ph.b[1], pl.b[1]);
                split_bf16(v.z, ph.b[2], pl.b[2]);
                split_bf16(v.w, ph.b[3], pl.b[3]);
                const size_t off = (size_t)m * KTOT + k;
                *reinterpret_cast<uint2*>(&g_Ah[off]) = ph.u;
                *reinterpret_cast<uint2*>(&g_Al[off]) = pl.u;
            } else {
                const unsigned n = (t - 1048576u) >> 8;   // logical n' (interleaved)
                const unsigned o  = n >> 3;
                const unsigned g  = (n >> 1) & 3;
                const unsigned ri = n & 1;
                const unsigned kk = q * 4u;               // k within segment (seg == s)
                const float* src;
                float sg;
                if (ri == 0) {
                    switch (s) {
                        case 0: src = Uw_r; sg =  1.0f; break;
                        case 1: src = Uw_i; sg = -1.0f; break;
                        case 2: src = Ww_r; sg =  1.0f; break;
                        default: src = Ww_i; sg = -1.0f; break;
                    }
                } else {
                    switch (s) {
                        case 0: src = Uw_i; sg = 1.0f; break;
                        case 1: src = Uw_r; sg = 1.0f; break;
                        case 2: src = Ww_i; sg = 1.0f; break;
                        default: src = Ww_r; sg = 1.0f; break;
                    }
                }
                float4 v = *reinterpret_cast<const float4*>(
                    src + (size_t)(g * 1024 + o) * 1024 + kk);
                union { __nv_bfloat16 b[4]; uint2 u; } ph, pl;
                split_bf16(sg * v.x, ph.b[0], pl.b[0]);
                split_bf16(sg * v.y, ph.b[1], pl.b[1]);
                split_bf16(sg * v.z, ph.b[2], pl.b[2]);
                split_bf16(sg * v.w, ph.b[3], pl.b[3]);
                const size_t off = (size_t)n * KTOT + k;
                *reinterpret_cast<uint2*>(&g_Bh[off]) = ph.u;
                *reinterpret_cast<uint2*>(&g_Bl[off]) = pl.u;
            }
        }
        __syncthreads();
        if (threadIdx.x == 0) {
            __threadfence();
            atomicAdd(&g_cnt[s], 1u);
        }
    }
}

// ---------------- init kernel: zero slab counters + combined bias ----------------
__global__ __launch_bounds__(256)
void clstm_init_kernel(const float* __restrict__ Ub_r, const float* __restrict__ Ub_i,
                       const float* __restrict__ Wb_r, const float* __restrict__ Wb_i) {
    const unsigned i = blockIdx.x * 256 + threadIdx.x;
    if (i < 4) g_cnt[i] = 0;
    if (i < NTOT) {
        const unsigned o  = i >> 3;
        const unsigned g  = (i >> 1) & 3;
        const unsigned ri = i & 1;
        const unsigned go = g * 1024 + o;
        g_biasC[i] = ri ? (Ub_i[go] + Wb_i[go]) : (Ub_r[go] + Wb_r[go]);
    }
}

// ---------------- host ----------------
typedef CUresult (*EncodeTiledFn)(
    CUtensorMap*, CUtensorMapDataType, cuuint32_t, void*,
    const cuuint64_t*, const cuuint64_t*, const cuuint32_t*, const cuuint32_t*,
    CUtensorMapInterleave, CUtensorMapSwizzle, CUtensorMapL2promotion,
    CUtensorMapFloatOOBfill);

static void make_map(EncodeTiledFn enc, CUtensorMap* tm, void* ptr,
                     unsigned rows, unsigned box_rows) {
    cuuint64_t dims[2]    = {(cuuint64_t)KTOT, (cuuint64_t)rows};
    cuuint64_t strides[1] = {(cuuint64_t)KTOT * 2};
    cuuint32_t box[2]     = {64u, box_rows};
    cuuint32_t es[2]      = {1u, 1u};
    enc(tm, CU_TENSOR_MAP_DATA_TYPE_BFLOAT16, 2, ptr,
        dims, strides, box, es,
        CU_TENSOR_MAP_INTERLEAVE_NONE, CU_TENSOR_MAP_SWIZZLE_128B,
        CU_TENSOR_MAP_L2_PROMOTION_L2_128B, CU_TENSOR_MAP_FLOAT_OOB_FILL_NONE);
}

extern "C" void kernel_launch(void* const* d_in, const int* in_sizes, int n_in,
                              void* d_out, int out_size)
{
    const float* input = (const float*)d_in[0];
    const float* h_x   = (const float*)d_in[1];
    const float* c_x   = (const float*)d_in[2];
    const float* Uw_r  = (const float*)d_in[3];
    const float* Uw_i  = (const float*)d_in[4];
    const float* Ub_r  = (const float*)d_in[5];
    const float* Ub_i  = (const float*)d_in[6];
    const float* Ww_r  = (const float*)d_in[7];
    const float* Ww_i  = (const float*)d_in[8];
    const float* Wb_r  = (const float*)d_in[9];
    const float* Wb_i  = (const float*)d_in[10];
    float* out = (float*)d_out;

    static cudaStream_t s_prep = nullptr;
    static cudaEvent_t ev_fork = nullptr, ev_join = nullptr;
    if (s_prep == nullptr) {
        cudaStreamCreateWithFlags(&s_prep, cudaStreamNonBlocking);
        cudaEventCreateWithFlags(&ev_fork, cudaEventDisableTiming);
        cudaEventCreateWithFlags(&ev_join, cudaEventDisableTiming);
    }

    void* fnp = nullptr;
    cudaDriverEntryPointQueryResult qr;
    cudaGetDriverEntryPointByVersion("cuTensorMapEncodeTiled", &fnp, 12000,
                                     cudaEnableDefault, &qr);
    EncodeTiledFn enc = (EncodeTiledFn)fnp;

    void *pAh, *pAl, *pBh, *pBl;
    cudaGetSymbolAddress(&pAh, g_Ah);
    cudaGetSymbolAddress(&pAl, g_Al);
    cudaGetSymbolAddress(&pBh, g_Bh);
    cudaGetSymbolAddress(&pBl, g_Bl);

    CUtensorMap tmAh, tmAl, tmBh, tmBl;
    make_map(enc, &tmAh, pAh, BDIM, 128);
    make_map(enc, &tmAl, pAl, BDIM, 128);
    make_map(enc, &tmBh, pBh, NTOT, 64);
    make_map(enc, &tmBl, pBl, NTOT, 64);

    cudaFuncSetAttribute(clstm_tc_gemm_kernel,
                         cudaFuncAttributeMaxDynamicSharedMemorySize, SMEM_BYTES);

    // init on stream 0; fork prep onto s_prep; gemm on stream 0 (concurrent).
    clstm_init_kernel<<<NTOT / 256, 256>>>(Ub_r, Ub_i, Wb_r, Wb_i);
    cudaEventRecord(ev_fork, 0);
    cudaStreamWaitEvent(s_prep, ev_fork, 0);
    prep_slab_kernel<<<PREP_BLOCKS, 256, 0, s_prep>>>(input, h_x, Uw_r, Uw_i, Ww_r, Ww_i);
    cudaEventRecord(ev_join, s_prep);

    dim3 grid(2 * NCLUST, 1, 1);   // 74 persistent 2-CTA clusters
    clstm_tc_gemm_kernel<<<grid, 256, SMEM_BYTES>>>(c_x, out, tmAh, tmAl, tmBh, tmBl);

    cudaStreamWaitEvent(0, ev_join, 0);   // join: graph ends after both
}

// round 14
// speedup vs baseline: 1.0639x; 1.0639x over previous
#include <cuda_runtime.h>
#include <cuda.h>
#include <cuda_bf16.h>

// CLSTM cell, persistent fused kernel, TMA edition (final best configuration):
//   prep (1 kernel): bf16 hi/lo split of X; sign-combined weights, N-interleaved
//                    n' = o*8 + g*2 + ri; combined bias.
//   gemm: 74 persistent 2-CTA clusters, 256x256 tiles, tcgen05 cg2 bf16 SS MMA,
//         3-stage pipeline fed by cta_group::2 TMA (complete_tx -> leader barrier),
//         double-buffered TMEM, LSTM epilogue fused at TMEM readback.

#define BDIM 4096
#define HDIM 1024
#define KTOT 4096
#define NTOT 8192

__device__ __align__(256) __nv_bfloat16 g_Ah[(size_t)BDIM * KTOT];
__device__ __align__(256) __nv_bfloat16 g_Al[(size_t)BDIM * KTOT];
__device__ __align__(256) __nv_bfloat16 g_Bh[(size_t)NTOT * KTOT];
__device__ __align__(256) __nv_bfloat16 g_Bl[(size_t)NTOT * KTOT];
__device__ float g_biasC[NTOT];
__device__ float g_z[(size_t)BDIM * NTOT];   // HMMA fallback only

__device__ __forceinline__ unsigned smem_to_u32(const void* p) {
    unsigned a;
    asm("{ .reg .u64 t; cvta.to.shared.u64 t, %1; cvt.u32.u64 %0, t; }"
        : "=r"(a) : "l"(p));
    return a;
}
__device__ __forceinline__ void cp_async16(unsigned dst, const void* src) {
    asm volatile("cp.async.cg.shared.global [%0], [%1], 16;"
        :: "r"(dst), "l"(src) : "memory");
}
#define CP_COMMIT() asm volatile("cp.async.commit_group;" ::: "memory")
#define CP_WAIT1()  asm volatile("cp.async.wait_group 1;" ::: "memory")

__device__ __forceinline__ float sigmoidf_(float x) {
    return 1.0f / (1.0f + expf(-x));
}
__device__ __forceinline__ void cell_math(const float zr0, const float zi0,
                                          const float zr1, const float zi1,
                                          const float zr2, const float zi2,
                                          const float zr3, const float zi3,
                                          const float cr, const float ci,
                                          float& htr, float& hti,
                                          float& ctr, float& cti) {
    const float fr = sigmoidf_(zr0), fi = sigmoidf_(zi0);
    const float ir = sigmoidf_(zr1), ii = sigmoidf_(zi1);
    const float ar = tanhf(zr2),     ai = tanhf(zi2);
    const float orr = sigmoidf_(zr3), oi = sigmoidf_(zi3);
    ctr = (cr * fr - ci * fi) + (ar * ir - ai * ii);
    cti = (cr * fi + ci * fr) + (ar * ii + ai * ir);
    const float tr = tanhf(ctr), ti = tanhf(cti);
    htr = orr * tr - oi * ti;
    hti = orr * ti + oi * tr;
}

#define NSTAGE 3
#define SMEM_BYTES (4096 + NSTAGE * 65536)
#define NTILES_TOT 512
#define NCLUST 74

__global__ __launch_bounds__(256, 1) __cluster_dims__(2, 1, 1)
void clstm_tc_gemm_kernel(const float* __restrict__ c_x, float* __restrict__ out,
                          const __grid_constant__ CUtensorMap tmAh,
                          const __grid_constant__ CUtensorMap tmAl,
                          const __grid_constant__ CUtensorMap tmBh,
                          const __grid_constant__ CUtensorMap tmBl) {
    extern __shared__ __align__(1024) char dsm[];
    const unsigned rank = blockIdx.x & 1;
    const unsigned cid  = blockIdx.x >> 1;               // 0..73
    const unsigned ntiles = (NTILES_TOT - 1 - cid) / NCLUST + 1;
    const int tid = threadIdx.x;

#ifdef __CUDA_ARCH_FEAT_SM103_ALL
    #define KCH 64
    #define NCHUNK (KTOT / KCH)
    #define STAGE_BYTES 65536
    #define A_H 0
    #define A_L 16384
    #define B_H 32768
    #define B_L 49152
    #define IDESC ((1u << 4) | (1u << 7) | (1u << 10) | (16u << 17) | (16u << 24))
    #define CHUNK_TX 131072u     // 2 CTAs x 64KB

    const unsigned base = smem_to_u32(dsm);
    const unsigned empB  = base + 0;      // 3 x 8B
    const unsigned xfB   = base + 24;     // 3 x 8B (leader's: TMA complete_tx)
    const unsigned accdB = base + 48;     // 2 x 8B
    const unsigned accfB = base + 64;     // 2 x 8B
    const unsigned tptr  = base + 80;
    float* sbias = (float*)(dsm + 1024);  // [2][256]
    const unsigned tiles = base + 4096;

    #define MBAR_INIT(a, c) \
        asm volatile("mbarrier.init.shared.b64 [%0], %1;" :: "r"(a), "r"((unsigned)(c)) : "memory")
    #define MBAR_EXPECT_TX(a, bytes) \
        asm volatile("mbarrier.arrive.expect_tx.shared.b64 _, [%0], %1;" \
            :: "r"(a), "r"((unsigned)(bytes)) : "memory")
    #define MBAR_WAIT(a, ph) do {                                                   \
        asm volatile("{\n\t.reg .pred P1;\n\t"                                      \
            "WL_%=:\n\t"                                                            \
            "mbarrier.try_wait.parity.acquire.cta.shared::cta.b64 P1, [%0], %1, 0x989680;\n\t" \
            "@P1 bra.uni WD_%=;\n\t"                                                \
            "bra.uni WL_%=;\n\t"                                                    \
            "WD_%=:\n\t}"                                                           \
            :: "r"(a), "r"((unsigned)(ph)) : "memory");                             \
    } while (0)
    #define MBAR_WAIT_CL(a, ph) do {                                                \
        asm volatile("{\n\t.reg .pred P1;\n\t"                                      \
            "WL_%=:\n\t"                                                            \
            "mbarrier.try_wait.parity.acquire.cluster.shared::cta.b64 P1, [%0], %1, 0x989680;\n\t" \
            "@P1 bra.uni WD_%=;\n\t"                                                \
            "bra.uni WL_%=;\n\t"                                                    \
            "WD_%=:\n\t}"                                                           \
            :: "r"(a), "r"((unsigned)(ph)) : "memory");                             \
    } while (0)
    #define CLUSTER_SYNC_() do {                                                    \
        asm volatile("barrier.cluster.arrive.aligned;" ::: "memory");               \
        asm volatile("barrier.cluster.wait.aligned;" ::: "memory");                 \
    } while (0)
    #define MMA_CG2(d, adesc, bdesc, en) \
        asm volatile("{\n\t.reg .pred p;\n\tsetp.ne.u32 p, %4, 0;\n\t"              \
            "tcgen05.mma.cta_group::2.kind::f16 [%0], %1, %2, %3, "                 \
            "{%5,%5,%5,%5,%5,%5,%5,%5}, p;\n\t}"                                    \
            :: "r"(d), "l"(adesc), "l"(bdesc), "r"(IDESC), "r"((unsigned)(en)),     \
               "r"(0u) : "memory")
    #define TMA2D_CG2(dst, map, cx, cy, mbar) \
        asm volatile("{\n\t.reg .b32 lb;\n\t"                                       \
            "and.b32 lb, %4, 0xFEFFFFFF;\n\t"                                       \
            "cp.async.bulk.tensor.2d.cta_group::2.shared::cluster.global"           \
            ".tile.mbarrier::complete_tx::bytes [%0], [%1, {%2, %3}], [lb];\n\t}"   \
            :: "r"(dst), "l"(map), "r"((int)(cx)), "r"((int)(cy)), "r"(mbar)        \
            : "memory")

    if (tid == 0) {
#pragma unroll
        for (int s = 0; s < NSTAGE; s++) {
            MBAR_INIT(empB + s * 8, 1);
            MBAR_INIT(xfB  + s * 8, 1);   // 1 arrive = leader's expect_tx
        }
        MBAR_INIT(accdB + 0, 1); MBAR_INIT(accdB + 8, 1);
        MBAR_INIT(accfB + 0, 2); MBAR_INIT(accfB + 8, 2);
    }
    if ((tid >> 5) == 4)   // warp 4 both CTAs: TMEM alloc, 512 cols (2 buffers)
        asm volatile("tcgen05.alloc.cta_group::2.sync.aligned.shared::cta.b32 [%0], %1;"
            :: "r"(tptr), "r"(512u) : "memory");
    __syncthreads();

    unsigned tmem;
    asm volatile("ld.shared.b32 %0, [%1];" : "=r"(tmem) : "r"(tptr));

    // leader arms the first NSTAGE rounds before any TMA can be issued
    if (rank == 0 && tid == 192) {
#pragma unroll
        for (int s = 0; s < NSTAGE; s++) MBAR_EXPECT_TX(xfB + s * 8, CHUNK_TX);
    }
    CLUSTER_SYNC_();

    if (tid < 128) {
        // ============ readback + fused LSTM epilogue (warps 0-3) ============
        const int lid = tid & 31;
        const unsigned woff = ((unsigned)(tid >> 5)) << 21;
        for (unsigned ti = 0; ti < ntiles; ti++) {
            const unsigned tile = ti * NCLUST + cid;
            const unsigned m0 = (tile >> 5) * 256;
            const unsigned n0 = (tile & 31) * 256;
            const unsigned b = ti & 1, u = ti >> 1;

            sbias[b * 256 + tid]       = g_biasC[n0 + tid];
            sbias[b * 256 + tid + 128] = g_biasC[n0 + tid + 128];

            MBAR_WAIT(accdB + b * 8, u & 1);
            asm volatile("tcgen05.fence::after_thread_sync;" ::: "memory");
            asm volatile("bar.sync 1, 128;" ::: "memory");

            const unsigned m = m0 + rank * 128 + (tid >> 5) * 32 + lid;
            const unsigned ob = n0 >> 3;
            const float* cxp = c_x + (size_t)m * 2048;
            const size_t hrow = (size_t)m * 2048;
            const size_t coff = (size_t)BDIM * 2048;
            const unsigned tb = tmem + b * 256 + woff;
#pragma unroll
            for (int j = 0; j < 8; j++) {
                unsigned r[32];
                asm volatile("tcgen05.ld.sync.aligned.32x32b.x32.b32 "
                    "{%0, %1, %2, %3, %4, %5, %6, %7, "
                    " %8, %9, %10, %11, %12, %13, %14, %15, "
                    " %16, %17, %18, %19, %20, %21, %22, %23, "
                    " %24, %25, %26, %27, %28, %29, %30, %31}, [%32];"
                    : "=r"(r[0]),  "=r"(r[1]),  "=r"(r[2]),  "=r"(r[3]),
                      "=r"(r[4]),  "=r"(r[5]),  "=r"(r[6]),  "=r"(r[7]),
                      "=r"(r[8]),  "=r"(r[9]),  "=r"(r[10]), "=r"(r[11]),
                      "=r"(r[12]), "=r"(r[13]), "=r"(r[14]), "=r"(r[15]),
                      "=r"(r[16]), "=r"(r[17]), "=r"(r[18]), "=r"(r[19]),
                      "=r"(r[20]), "=r"(r[21]), "=r"(r[22]), "=r"(r[23]),
                      "=r"(r[24]), "=r"(r[25]), "=r"(r[26]), "=r"(r[27]),
                      "=r"(r[28]), "=r"(r[29]), "=r"(r[30]), "=r"(r[31])
                    : "r"(tb + j * 32));
                asm volatile("tcgen05.wait::ld.sync.aligned;" ::: "memory");

                const unsigned o4 = ob + j * 4;
                const float4 cr4 = *reinterpret_cast<const float4*>(cxp + o4);
                const float4 ci4 = *reinterpret_cast<const float4*>(cxp + 1024 + o4);
                float htr[4], hti[4], ctr[4], cti[4];
#pragma unroll
                for (int q = 0; q < 4; q++) {
                    const int c0 = q * 8;
                    const float* sbp = sbias + b * 256 + j * 32 + c0;
                    cell_math(
                        __uint_as_float(r[c0 + 0]) + sbp[0], __uint_as_float(r[c0 + 1]) + sbp[1],
                        __uint_as_float(r[c0 + 2]) + sbp[2], __uint_as_float(r[c0 + 3]) + sbp[3],
                        __uint_as_float(r[c0 + 4]) + sbp[4], __uint_as_float(r[c0 + 5]) + sbp[5],
                        __uint_as_float(r[c0 + 6]) + sbp[6], __uint_as_float(r[c0 + 7]) + sbp[7],
                        (&cr4.x)[q], (&ci4.x)[q],
                        htr[q], hti[q], ctr[q], cti[q]);
                }
                *reinterpret_cast<float4*>(out + hrow + o4) =
                    make_float4(htr[0], htr[1], htr[2], htr[3]);
                *reinterpret_cast<float4*>(out + hrow + 1024 + o4) =
                    make_float4(hti[0], hti[1], hti[2], hti[3]);
                *reinterpret_cast<float4*>(out + coff + hrow + o4) =
                    make_float4(ctr[0], ctr[1], ctr[2], ctr[3]);
                *reinterpret_cast<float4*>(out + coff + hrow + 1024 + o4) =
                    make_float4(cti[0], cti[1], cti[2], cti[3]);
            }
            asm volatile("tcgen05.fence::before_thread_sync;" ::: "memory");
            asm volatile("bar.sync 1, 128;" ::: "memory");
            if (tid == 0) {
                asm volatile("{\n\t.reg .b32 rem;\n\t"
                    "mapa.shared::cluster.u32 rem, %0, 0;\n\t"
                    "mbarrier.arrive.release.cluster.shared::cluster.b64 _, [rem];\n\t}"
                    :: "r"(accfB + b * 8) : "memory");
            }
        }
    } else if (tid == 128) {
        // ============ TMA issuer (both CTAs), 6 loads per chunk ============
        unsigned ci = 0;
        for (unsigned ti = 0; ti < ntiles; ti++) {
            const unsigned tile = ti * NCLUST + cid;
            const unsigned m0 = (tile >> 5) * 256;
            const unsigned n0 = (tile & 31) * 256;
            const int yA  = (int)(m0 + rank * 128);
            const int yB0 = (int)(n0 + rank * 64);
            const int yB1 = (int)(n0 + 128 + rank * 64);
            for (int i = 0; i < NCHUNK; i++, ci++) {
                const unsigned s = ci % NSTAGE, w = ci / NSTAGE;
                if (w >= 1) MBAR_WAIT(empB + s * 8, (w - 1) & 1);
                const unsigned sb = tiles + s * STAGE_BYTES;
                const int k0 = i * KCH;
                const unsigned mb = xfB + s * 8;
                TMA2D_CG2(sb + A_H,        &tmAh, k0, yA,  mb);
                TMA2D_CG2(sb + A_L,        &tmAl, k0, yA,  mb);
                TMA2D_CG2(sb + B_H,        &tmBh, k0, yB0, mb);
                TMA2D_CG2(sb + B_H + 8192, &tmBh, k0, yB1, mb);
                TMA2D_CG2(sb + B_L,        &tmBl, k0, yB0, mb);
                TMA2D_CG2(sb + B_L + 8192, &tmBl, k0, yB1, mb);
            }
        }
    } else if (tid == 192 && rank == 0) {
        // ============ MMA issue thread (leader only) ============
        const unsigned long long DBASE =
            (2ull << 61) | (1ull << 46) | (64ull << 32) | (1ull << 16);
        unsigned ci = 0;
        for (unsigned ti = 0; ti < ntiles; ti++) {
            const unsigned b = ti & 1;
            if (ti >= 2) MBAR_WAIT_CL(accfB + b * 8, ((ti - 2) >> 1) & 1);
            const unsigned dbase = tmem + b * 256;
            for (int i = 0; i < NCHUNK; i++, ci++) {
                const unsigned s = ci % NSTAGE, w = ci / NSTAGE;
                MBAR_WAIT_CL(xfB + s * 8, w & 1);
                MBAR_EXPECT_TX(xfB + s * 8, CHUNK_TX);   // arm next round
                const unsigned sb = tiles + s * STAGE_BYTES;
                const unsigned long long ah = DBASE | ((unsigned long long)((sb + A_H) >> 4) & 0x3FFF);
                const unsigned long long al = DBASE | ((unsigned long long)((sb + A_L) >> 4) & 0x3FFF);
                const unsigned long long bh = DBASE | ((unsigned long long)((sb + B_H) >> 4) & 0x3FFF);
                const unsigned long long bl = DBASE | ((unsigned long long)((sb + B_L) >> 4) & 0x3FFF);
#pragma unroll
                for (int half = 0; half < 2; half++) {
                    const unsigned d = dbase + half * 128;
                    const unsigned long long bo = (unsigned long long)half * 512;
#pragma unroll
                    for (int ks = 0; ks < 4; ks++)
                        MMA_CG2(d, ah + ks * 2, bh + bo + ks * 2,
                                (i == 0 && ks == 0) ? 0u : 1u);
#pragma unroll
                    for (int ks = 0; ks < 4; ks++)
                        MMA_CG2(d, ah + ks * 2, bl + bo + ks * 2, 1u);
#pragma unroll
                    for (int ks = 0; ks < 4; ks++)
                        MMA_CG2(d, al + ks * 2, bh + bo + ks * 2, 1u);
                }
                asm volatile("tcgen05.commit.cta_group::2.mbarrier::arrive::one"
                    ".shared::cluster.multicast::cluster.b64 [%0], %1;"
                    :: "r"(empB + s * 8), "h"((unsigned short)0x3) : "memory");
            }
            asm volatile("tcgen05.commit.cta_group::2.mbarrier::arrive::one"
                ".shared::cluster.multicast::cluster.b64 [%0], %1;"
                :: "r"(accdB + b * 8), "h"((unsigned short)0x3) : "memory");
        }
    }
    __syncthreads();
    if ((tid >> 5) == 4) {
        asm volatile("tcgen05.relinquish_alloc_permit.cta_group::2.sync.aligned;");
        asm volatile("tcgen05.dealloc.cta_group::2.sync.aligned.b32 %0, %1;"
            :: "r"(tmem), "r"(512u));
    }
    CLUSTER_SYNC_();

#else
    // ======== HMMA fallback (plain sm_103; never selected on GB300) ========
    #define HKC 32
    #define HNCH (KTOT / HKC)
    #define HSTG 40960
    #define HA_H 0
    #define HA_L 10240
    #define HB_H 20480
    #define HB_L 30720
    #define RST 80

    const int lane = tid & 31;
    const int w = tid >> 5;
    const unsigned base = smem_to_u32(dsm);
    const unsigned m_base = (unsigned)(w & 1) * 64;
    const unsigned n_base = (unsigned)(w >> 1) * 32;

    #define LDSM_X4(r0, r1, r2, r3, addr) \
        asm volatile("ldmatrix.sync.aligned.m8n8.x4.shared.b16 {%0,%1,%2,%3}, [%4];" \
            : "=r"(r0), "=r"(r1), "=r"(r2), "=r"(r3) : "r"(addr))
    #define LDSM_X2(r0, r1, addr) \
        asm volatile("ldmatrix.sync.aligned.m8n8.x2.shared.b16 {%0,%1}, [%2];" \
            : "=r"(r0), "=r"(r1) : "r"(addr))
    #define MMA_BF16(ac, av, bv) \
        asm volatile("mma.sync.aligned.m16n8k16.row.col.f32.bf16.bf16.f32 " \
            "{%0,%1,%2,%3}, {%4,%5,%6,%7}, {%8,%9}, {%0,%1,%2,%3};" \
            : "+f"((ac)[0]), "+f"((ac)[1]), "+f"((ac)[2]), "+f"((ac)[3]) \
            : "r"((av)[0]), "r"((av)[1]), "r"((av)[2]), "r"((av)[3]), \
              "r"((bv)[0]), "r"((bv)[1]))

    for (unsigned ti = 0; ti < ntiles; ti++) {
        const unsigned tile = ti * NCLUST + cid;
        const unsigned m0 = (tile >> 5) * 256;
        const unsigned n0 = (tile & 31) * 256;
        const unsigned fm0 = m0 + rank * 128;

        for (int nh = 0; nh < 2; nh++) {
            const unsigned n0h = n0 + nh * 128;
            float acc[4][4][4];
#pragma unroll
            for (int a = 0; a < 4; a++)
#pragma unroll
                for (int bq = 0; bq < 4; bq++)
#pragma unroll
                    for (int c = 0; c < 4; c++) acc[a][bq][c] = 0.0f;

            auto load_stage = [&](unsigned sb, unsigned k0) {
                for (unsigned idx = (unsigned)tid; idx < 2048; idx += 256) {
                    const unsigned mat = idx >> 9;
                    const unsigned rem = idx & 511;
                    const unsigned row = rem >> 2;
                    const unsigned c = rem & 3;
                    const __nv_bfloat16* src;
                    if (mat == 0)      src = g_Ah + (size_t)(fm0 + row) * KTOT + k0 + c * 8;
                    else if (mat == 1) src = g_Al + (size_t)(fm0 + row) * KTOT + k0 + c * 8;
                    else if (mat == 2) src = g_Bh + (size_t)(n0h + row) * KTOT + k0 + c * 8;
                    else               src = g_Bl + (size_t)(n0h + row) * KTOT + k0 + c * 8;
                    cp_async16(sb + mat * 10240 + row * RST + c * 16, src);
                }
            };

            load_stage(base + 0 * HSTG, 0);   CP_COMMIT();
            load_stage(base + 1 * HSTG, HKC); CP_COMMIT();

            for (int i = 0; i < HNCH; i++) {
                CP_WAIT1();
                __syncthreads();
                if (i + 2 < HNCH) load_stage(base + (unsigned)((i + 2) % 3) * HSTG, (i + 2) * HKC);
                CP_COMMIT();

                const unsigned sb = base + (unsigned)(i % 3) * HSTG;
#pragma unroll
                for (int ks = 0; ks < 2; ks++) {
                    unsigned a[4][4], bhv[4][2], blv[4][2];
                    const unsigned acol = (unsigned)(ks * 2 + (lane >> 4)) * 16;
                    const unsigned bcol = (unsigned)(ks * 2 + ((lane >> 3) & 1)) * 16;
#pragma unroll
                    for (int mt = 0; mt < 4; mt++) {
                        const unsigned ad = sb + HA_H
                            + (m_base + mt * 16 + (lane & 15)) * RST + acol;
                        LDSM_X4(a[mt][0], a[mt][1], a[mt][2], a[mt][3], ad);
                    }
#pragma unroll
                    for (int nt = 0; nt < 4; nt++) {
                        const unsigned brow = (n_base + nt * 8 + (lane & 7)) * RST + bcol;
                        LDSM_X2(bhv[nt][0], bhv[nt][1], sb + HB_H + brow);
                        LDSM_X2(blv[nt][0], blv[nt][1], sb + HB_L + brow);
                    }
#pragma unroll
                    for (int mt = 0; mt < 4; mt++)
#pragma unroll
                        for (int nt = 0; nt < 4; nt++) {
                            MMA_BF16(acc[mt][nt], a[mt], bhv[nt]);
                            MMA_BF16(acc[mt][nt], a[mt], blv[nt]);
                        }
#pragma unroll
                    for (int mt = 0; mt < 4; mt++) {
                        const unsigned ad = sb + HA_L
                            + (m_base + mt * 16 + (lane & 15)) * RST + acol;
                        LDSM_X4(a[mt][0], a[mt][1], a[mt][2], a[mt][3], ad);
                    }
#pragma unroll
                    for (int mt = 0; mt < 4; mt++)
#pragma unroll
                        for (int nt = 0; nt < 4; nt++)
                            MMA_BF16(acc[mt][nt], a[mt], bhv[nt]);
                }
                __syncthreads();
            }

#pragma unroll
            for (int mt = 0; mt < 4; mt++) {
                const unsigned row0 = fm0 + m_base + mt * 16 + (lane >> 2);
#pragma unroll
                for (int nt = 0; nt < 4; nt++) {
                    const unsigned col = n0h + n_base + nt * 8 + 2 * (lane & 3);
                    *reinterpret_cast<float2*>(&g_z[(size_t)row0 * NTOT + col]) =
                        make_float2(acc[mt][nt][0], acc[mt][nt][1]);
                    *reinterpret_cast<float2*>(&g_z[(size_t)(row0 + 8) * NTOT + col]) =
                        make_float2(acc[mt][nt][2], acc[mt][nt][3]);
                }
            }
            __syncthreads();
        }

        for (int e = tid; e < 128 * 32; e += 256) {
            const unsigned rr = e >> 5, oq = e & 31;
            const unsigned m = fm0 + rr;
            const unsigned o = (n0 >> 3) + oq;
            const float* zp = g_z + (size_t)m * NTOT + n0 + oq * 8;
            const float* bp = g_biasC + n0 + oq * 8;
            const float cr = c_x[(size_t)m * 2048 + o];
            const float ci = c_x[(size_t)m * 2048 + 1024 + o];
            float htr, hti, ctr, cti;
            cell_math(zp[0] + bp[0], zp[1] + bp[1], zp[2] + bp[2], zp[3] + bp[3],
                      zp[4] + bp[4], zp[5] + bp[5], zp[6] + bp[6], zp[7] + bp[7],
                      cr, ci, htr, hti, ctr, cti);
            const size_t hrow = (size_t)m * 2048;
            const size_t coff = (size_t)BDIM * 2048;
            out[hrow + o] = htr;
            out[hrow + 1024 + o] = hti;
            out[coff + hrow + o] = ctr;
            out[coff + hrow + 1024 + o] = cti;
        }
        __syncthreads();
    }
#endif
}

// ---------------- merged prep kernel ----------------
__device__ __forceinline__ void split_bf16(float v, __nv_bfloat16& hi, __nv_bfloat16& lo) {
    hi = __float2bfloat16_rn(v);
    lo = __float2bfloat16_rn(v - __bfloat162float(hi));
}

#define ACT_BLKS 16384
#define W_BLKS 32768

__global__ __launch_bounds__(256)
void prep_all_kernel(const float* __restrict__ input, const float* __restrict__ h_x,
                     const float* __restrict__ Uw_r, const float* __restrict__ Uw_i,
                     const float* __restrict__ Ww_r, const float* __restrict__ Ww_i,
                     const float* __restrict__ Ub_r, const float* __restrict__ Ub_i,
                     const float* __restrict__ Wb_r, const float* __restrict__ Wb_i) {
    const unsigned bid = blockIdx.x;
    if (bid < ACT_BLKS) {
        const unsigned idx = bid * 256 + threadIdx.x;
        const unsigned m = idx >> 10;
        const unsigned k = (idx & 1023) * 4;
        const float* src = (k < 2048) ? (input + (size_t)m * 2048 + k)
                                      : (h_x   + (size_t)m * 2048 + (k - 2048));
        float4 v = *reinterpret_cast<const float4*>(src);
        union { __nv_bfloat16 b[4]; uint2 u; } ph, pl;
        split_bf16(v.x, ph.b[0], pl.b[0]);
        split_bf16(v.y, ph.b[1], pl.b[1]);
        split_bf16(v.z, ph.b[2], pl.b[2]);
        split_bf16(v.w, ph.b[3], pl.b[3]);
        const size_t off = (size_t)m * KTOT + k;
        *reinterpret_cast<uint2*>(&g_Ah[off]) = ph.u;
        *reinterpret_cast<uint2*>(&g_Al[off]) = pl.u;
    } else if (bid < ACT_BLKS + W_BLKS) {
        const unsigned idx = (bid - ACT_BLKS) * 256 + threadIdx.x;
        const unsigned n = idx >> 10;              // n' (interleaved)
        const unsigned k = (idx & 1023) * 4;
        const unsigned o  = n >> 3;
        const unsigned g  = (n >> 1) & 3;
        const unsigned ri = n & 1;
        const unsigned seg = k >> 10, kk = k & 1023;

        const float* src;
        float s;
        if (ri == 0) {
            switch (seg) {
                case 0: src = Uw_r; s =  1.0f; break;
                case 1: src = Uw_i; s = -1.0f; break;
                case 2: src = Ww_r; s =  1.0f; break;
                default: src = Ww_i; s = -1.0f; break;
            }
        } else {
            switch (seg) {
                case 0: src = Uw_i; s = 1.0f; break;
                case 1: src = Uw_r; s = 1.0f; break;
                case 2: src = Ww_i; s = 1.0f; break;
                default: src = Ww_r; s = 1.0f; break;
            }
        }
        float4 v = *reinterpret_cast<const float4*>(src + ((size_t)(g * 1024 + o)) * 1024 + kk);
        union { __nv_bfloat16 b[4]; uint2 u; } ph, pl;
        split_bf16(s * v.x, ph.b[0], pl.b[0]);
        split_bf16(s * v.y, ph.b[1], pl.b[1]);
        split_bf16(s * v.z, ph.b[2], pl.b[2]);
        split_bf16(s * v.w, ph.b[3], pl.b[3]);
        const size_t off = (size_t)n * KTOT + k;
        *reinterpret_cast<uint2*>(&g_Bh[off]) = ph.u;
        *reinterpret_cast<uint2*>(&g_Bl[off]) = pl.u;
    } else {
        const unsigned n = (bid - ACT_BLKS - W_BLKS) * 256 + threadIdx.x;
        const unsigned o  = n >> 3;
        const unsigned g  = (n >> 1) & 3;
        const unsigned ri = n & 1;
        const unsigned go = g * 1024 + o;
        g_biasC[n] = ri ? (Ub_i[go] + Wb_i[go]) : (Ub_r[go] + Wb_r[go]);
    }
}

// ---------------- host ----------------
typedef CUresult (*EncodeTiledFn)(
    CUtensorMap*, CUtensorMapDataType, cuuint32_t, void*,
    const cuuint64_t*, const cuuint64_t*, const cuuint32_t*, const cuuint32_t*,
    CUtensorMapInterleave, CUtensorMapSwizzle, CUtensorMapL2promotion,
    CUtensorMapFloatOOBfill);

static void make_map(EncodeTiledFn enc, CUtensorMap* tm, void* ptr,
                     unsigned rows, unsigned box_rows) {
    cuuint64_t dims[2]    = {(cuuint64_t)KTOT, (cuuint64_t)rows};
    cuuint64_t strides[1] = {(cuuint64_t)KTOT * 2};
    cuuint32_t box[2]     = {64u, box_rows};       // 64 bf16 = 128B (SW128)
    cuuint32_t es[2]      = {1u, 1u};
    enc(tm, CU_TENSOR_MAP_DATA_TYPE_BFLOAT16, 2, ptr,
        dims, strides, box, es,
        CU_TENSOR_MAP_INTERLEAVE_NONE, CU_TENSOR_MAP_SWIZZLE_128B,
        CU_TENSOR_MAP_L2_PROMOTION_L2_128B, CU_TENSOR_MAP_FLOAT_OOB_FILL_NONE);
}

extern "C" void kernel_launch(void* const* d_in, const int* in_sizes, int n_in,
                              void* d_out, int out_size)
{
    const float* input = (const float*)d_in[0];
    const float* h_x   = (const float*)d_in[1];
    const float* c_x   = (const float*)d_in[2];
    const float* Uw_r  = (const float*)d_in[3];
    const float* Uw_i  = (const float*)d_in[4];
    const float* Ub_r  = (const float*)d_in[5];
    const float* Ub_i  = (const float*)d_in[6];
    const float* Ww_r  = (const float*)d_in[7];
    const float* Ww_i  = (const float*)d_in[8];
    const float* Wb_r  = (const float*)d_in[9];
    const float* Wb_i  = (const float*)d_in[10];
    float* out = (float*)d_out;

    // tensormaps (host-built each call; capture-time only)
    void* fnp = nullptr;
    cudaDriverEntryPointQueryResult qr;
    cudaGetDriverEntryPointByVersion("cuTensorMapEncodeTiled", &fnp, 12000,
                                     cudaEnableDefault, &qr);
    EncodeTiledFn enc = (EncodeTiledFn)fnp;

    void *pAh, *pAl, *pBh, *pBl;
    cudaGetSymbolAddress(&pAh, g_Ah);
    cudaGetSymbolAddress(&pAl, g_Al);
    cudaGetSymbolAddress(&pBh, g_Bh);
    cudaGetSymbolAddress(&pBl, g_Bl);

    CUtensorMap tmAh, tmAl, tmBh, tmBl;
    make_map(enc, &tmAh, pAh, BDIM, 128);
    make_map(enc, &tmAl, pAl, BDIM, 128);
    make_map(enc, &tmBh, pBh, NTOT, 64);
    make_map(enc, &tmBl, pBl, NTOT, 64);

    cudaFuncSetAttribute(clstm_tc_gemm_kernel,
                         cudaFuncAttributeMaxDynamicSharedMemorySize, SMEM_BYTES);

    prep_all_kernel<<<ACT_BLKS + W_BLKS + NTOT / 256, 256>>>(
        input, h_x, Uw_r, Uw_i, Ww_r, Ww_i, Ub_r, Ub_i, Wb_r, Wb_i);

    dim3 grid(2 * NCLUST, 1, 1);   // 74 persistent 2-CTA clusters
    clstm_tc_gemm_kernel<<<grid, 256, SMEM_BYTES>>>(c_x, out, tmAh, tmAl, tmBh, tmBl);
}

// round 15
// speedup vs baseline: 1.0819x; 1.0170x over previous
#include <cuda_runtime.h>
#include <cuda.h>
#include <cuda_bf16.h>

// CLSTM cell, persistent fused kernel, TMA edition (best config + relaxed
// producer-side mbarrier waits):
//   prep (1 kernel): bf16 hi/lo split of X; sign-combined weights, N-interleaved
//                    n' = o*8 + g*2 + ri; combined bias.
//   gemm: 74 persistent 2-CTA clusters, 256x256 tiles, tcgen05 cg2 bf16 SS MMA,
//         3-stage pipeline fed by cta_group::2 TMA (complete_tx -> leader barrier),
//         double-buffered TMEM, LSTM epilogue fused at TMEM readback.

#define BDIM 4096
#define HDIM 1024
#define KTOT 4096
#define NTOT 8192

__device__ __align__(256) __nv_bfloat16 g_Ah[(size_t)BDIM * KTOT];
__device__ __align__(256) __nv_bfloat16 g_Al[(size_t)BDIM * KTOT];
__device__ __align__(256) __nv_bfloat16 g_Bh[(size_t)NTOT * KTOT];
__device__ __align__(256) __nv_bfloat16 g_Bl[(size_t)NTOT * KTOT];
__device__ float g_biasC[NTOT];
__device__ float g_z[(size_t)BDIM * NTOT];   // HMMA fallback only

__device__ __forceinline__ unsigned smem_to_u32(const void* p) {
    unsigned a;
    asm("{ .reg .u64 t; cvta.to.shared.u64 t, %1; cvt.u32.u64 %0, t; }"
        : "=r"(a) : "l"(p));
    return a;
}
__device__ __forceinline__ void cp_async16(unsigned dst, const void* src) {
    asm volatile("cp.async.cg.shared.global [%0], [%1], 16;"
        :: "r"(dst), "l"(src) : "memory");
}
#define CP_COMMIT() asm volatile("cp.async.commit_group;" ::: "memory")
#define CP_WAIT1()  asm volatile("cp.async.wait_group 1;" ::: "memory")

__device__ __forceinline__ float sigmoidf_(float x) {
    return 1.0f / (1.0f + expf(-x));
}
__device__ __forceinline__ void cell_math(const float zr0, const float zi0,
                                          const float zr1, const float zi1,
                                          const float zr2, const float zi2,
                                          const float zr3, const float zi3,
                                          const float cr, const float ci,
                                          float& htr, float& hti,
                                          float& ctr, float& cti) {
    const float fr = sigmoidf_(zr0), fi = sigmoidf_(zi0);
    const float ir = sigmoidf_(zr1), ii = sigmoidf_(zi1);
    const float ar = tanhf(zr2),     ai = tanhf(zi2);
    const float orr = sigmoidf_(zr3), oi = sigmoidf_(zi3);
    ctr = (cr * fr - ci * fi) + (ar * ir - ai * ii);
    cti = (cr * fi + ci * fr) + (ar * ii + ai * ir);
    const float tr = tanhf(ctr), ti = tanhf(cti);
    htr = orr * tr - oi * ti;
    hti = orr * ti + oi * tr;
}

#define NSTAGE 3
#define SMEM_BYTES (4096 + NSTAGE * 65536)
#define NTILES_TOT 512
#define NCLUST 74

__global__ __launch_bounds__(256, 1) __cluster_dims__(2, 1, 1)
void clstm_tc_gemm_kernel(const float* __restrict__ c_x, float* __restrict__ out,
                          const __grid_constant__ CUtensorMap tmAh,
                          const __grid_constant__ CUtensorMap tmAl,
                          const __grid_constant__ CUtensorMap tmBh,
                          const __grid_constant__ CUtensorMap tmBl) {
    extern __shared__ __align__(1024) char dsm[];
    const unsigned rank = blockIdx.x & 1;
    const unsigned cid  = blockIdx.x >> 1;               // 0..73
    const unsigned ntiles = (NTILES_TOT - 1 - cid) / NCLUST + 1;
    const int tid = threadIdx.x;

#ifdef __CUDA_ARCH_FEAT_SM103_ALL
    #define KCH 64
    #define NCHUNK (KTOT / KCH)
    #define STAGE_BYTES 65536
    #define A_H 0
    #define A_L 16384
    #define B_H 32768
    #define B_L 49152
    #define IDESC ((1u << 4) | (1u << 7) | (1u << 10) | (16u << 17) | (16u << 24))
    #define CHUNK_TX 131072u     // 2 CTAs x 64KB

    const unsigned base = smem_to_u32(dsm);
    const unsigned empB  = base + 0;      // 3 x 8B
    const unsigned xfB   = base + 24;     // 3 x 8B (leader's: TMA complete_tx)
    const unsigned accdB = base + 48;     // 2 x 8B
    const unsigned accfB = base + 64;     // 2 x 8B
    const unsigned tptr  = base + 80;
    float* sbias = (float*)(dsm + 1024);  // [2][256]
    const unsigned tiles = base + 4096;

    #define MBAR_INIT(a, c) \
        asm volatile("mbarrier.init.shared.b64 [%0], %1;" :: "r"(a), "r"((unsigned)(c)) : "memory")
    #define MBAR_EXPECT_TX(a, bytes) \
        asm volatile("mbarrier.arrive.expect_tx.shared.b64 _, [%0], %1;" \
            :: "r"(a), "r"((unsigned)(bytes)) : "memory")
    #define MBAR_WAIT(a, ph) do {                                                   \
        asm volatile("{\n\t.reg .pred P1;\n\t"                                      \
            "WL_%=:\n\t"                                                            \
            "mbarrier.try_wait.parity.acquire.cta.shared::cta.b64 P1, [%0], %1, 0x989680;\n\t" \
            "@P1 bra.uni WD_%=;\n\t"                                                \
            "bra.uni WL_%=;\n\t"                                                    \
            "WD_%=:\n\t}"                                                           \
            :: "r"(a), "r"((unsigned)(ph)) : "memory");                             \
    } while (0)
    // relaxed variant: safe ONLY when all post-wait SMEM accesses are
    // async-proxy (TMA issue / tcgen05.mma) — producer-side waits.
    #define MBAR_WAIT_RLX(a, ph) do {                                               \
        asm volatile("{\n\t.reg .pred P1;\n\t"                                      \
            "WL_%=:\n\t"                                                            \
            "mbarrier.try_wait.parity.relaxed.cta.shared::cta.b64 P1, [%0], %1, 0x989680;\n\t" \
            "@P1 bra.uni WD_%=;\n\t"                                                \
            "bra.uni WL_%=;\n\t"                                                    \
            "WD_%=:\n\t}"                                                           \
            :: "r"(a), "r"((unsigned)(ph)) : "memory");                             \
    } while (0)
    #define MBAR_WAIT_CL(a, ph) do {                                                \
        asm volatile("{\n\t.reg .pred P1;\n\t"                                      \
            "WL_%=:\n\t"                                                            \
            "mbarrier.try_wait.parity.acquire.cluster.shared::cta.b64 P1, [%0], %1, 0x989680;\n\t" \
            "@P1 bra.uni WD_%=;\n\t"                                                \
            "bra.uni WL_%=;\n\t"                                                    \
            "WD_%=:\n\t}"                                                           \
            :: "r"(a), "r"((unsigned)(ph)) : "memory");                             \
    } while (0)
    #define MBAR_WAIT_CL_RLX(a, ph) do {                                            \
        asm volatile("{\n\t.reg .pred P1;\n\t"                                      \
            "WL_%=:\n\t"                                                            \
            "mbarrier.try_wait.parity.relaxed.cluster.shared::cta.b64 P1, [%0], %1, 0x989680;\n\t" \
            "@P1 bra.uni WD_%=;\n\t"                                                \
            "bra.uni WL_%=;\n\t"                                                    \
            "WD_%=:\n\t}"                                                           \
            :: "r"(a), "r"((unsigned)(ph)) : "memory");                             \
    } while (0)
    #define CLUSTER_SYNC_() do {                                                    \
        asm volatile("barrier.cluster.arrive.aligned;" ::: "memory");               \
        asm volatile("barrier.cluster.wait.aligned;" ::: "memory");                 \
    } while (0)
    #define MMA_CG2(d, adesc, bdesc, en) \
        asm volatile("{\n\t.reg .pred p;\n\tsetp.ne.u32 p, %4, 0;\n\t"              \
            "tcgen05.mma.cta_group::2.kind::f16 [%0], %1, %2, %3, "                 \
            "{%5,%5,%5,%5,%5,%5,%5,%5}, p;\n\t}"                                    \
            :: "r"(d), "l"(adesc), "l"(bdesc), "r"(IDESC), "r"((unsigned)(en)),     \
               "r"(0u) : "memory")
    #define TMA2D_CG2(dst, map, cx, cy, mbar) \
        asm volatile("{\n\t.reg .b32 lb;\n\t"                                       \
            "and.b32 lb, %4, 0xFEFFFFFF;\n\t"                                       \
            "cp.async.bulk.tensor.2d.cta_group::2.shared::cluster.global"           \
            ".tile.mbarrier::complete_tx::bytes [%0], [%1, {%2, %3}], [lb];\n\t}"   \
            :: "r"(dst), "l"(map), "r"((int)(cx)), "r"((int)(cy)), "r"(mbar)        \
            : "memory")

    if (tid == 0) {
#pragma unroll
        for (int s = 0; s < NSTAGE; s++) {
            MBAR_INIT(empB + s * 8, 1);
            MBAR_INIT(xfB  + s * 8, 1);   // 1 arrive = leader's expect_tx
        }
        MBAR_INIT(accdB + 0, 1); MBAR_INIT(accdB + 8, 1);
        MBAR_INIT(accfB + 0, 2); MBAR_INIT(accfB + 8, 2);
    }
    if ((tid >> 5) == 4)   // warp 4 both CTAs: TMEM alloc, 512 cols (2 buffers)
        asm volatile("tcgen05.alloc.cta_group::2.sync.aligned.shared::cta.b32 [%0], %1;"
            :: "r"(tptr), "r"(512u) : "memory");
    __syncthreads();

    unsigned tmem;
    asm volatile("ld.shared.b32 %0, [%1];" : "=r"(tmem) : "r"(tptr));

    // leader arms the first NSTAGE rounds before any TMA can be issued
    if (rank == 0 && tid == 192) {
#pragma unroll
        for (int s = 0; s < NSTAGE; s++) MBAR_EXPECT_TX(xfB + s * 8, CHUNK_TX);
    }
    CLUSTER_SYNC_();

    if (tid < 128) {
        // ============ readback + fused LSTM epilogue (warps 0-3) ============
        const int lid = tid & 31;
        const unsigned woff = ((unsigned)(tid >> 5)) << 21;
        for (unsigned ti = 0; ti < ntiles; ti++) {
            const unsigned tile = ti * NCLUST + cid;
            const unsigned m0 = (tile >> 5) * 256;
            const unsigned n0 = (tile & 31) * 256;
            const unsigned b = ti & 1, u = ti >> 1;

            sbias[b * 256 + tid]       = g_biasC[n0 + tid];
            sbias[b * 256 + tid + 128] = g_biasC[n0 + tid + 128];

            MBAR_WAIT(accdB + b * 8, u & 1);
            asm volatile("tcgen05.fence::after_thread_sync;" ::: "memory");
            asm volatile("bar.sync 1, 128;" ::: "memory");

            const unsigned m = m0 + rank * 128 + (tid >> 5) * 32 + lid;
            const unsigned ob = n0 >> 3;
            const float* cxp = c_x + (size_t)m * 2048;
            const size_t hrow = (size_t)m * 2048;
            const size_t coff = (size_t)BDIM * 2048;
            const unsigned tb = tmem + b * 256 + woff;
#pragma unroll
            for (int j = 0; j < 8; j++) {
                unsigned r[32];
                asm volatile("tcgen05.ld.sync.aligned.32x32b.x32.b32 "
                    "{%0, %1, %2, %3, %4, %5, %6, %7, "
                    " %8, %9, %10, %11, %12, %13, %14, %15, "
                    " %16, %17, %18, %19, %20, %21, %22, %23, "
                    " %24, %25, %26, %27, %28, %29, %30, %31}, [%32];"
                    : "=r"(r[0]),  "=r"(r[1]),  "=r"(r[2]),  "=r"(r[3]),
                      "=r"(r[4]),  "=r"(r[5]),  "=r"(r[6]),  "=r"(r[7]),
                      "=r"(r[8]),  "=r"(r[9]),  "=r"(r[10]), "=r"(r[11]),
                      "=r"(r[12]), "=r"(r[13]), "=r"(r[14]), "=r"(r[15]),
                      "=r"(r[16]), "=r"(r[17]), "=r"(r[18]), "=r"(r[19]),
                      "=r"(r[20]), "=r"(r[21]), "=r"(r[22]), "=r"(r[23]),
                      "=r"(r[24]), "=r"(r[25]), "=r"(r[26]), "=r"(r[27]),
                      "=r"(r[28]), "=r"(r[29]), "=r"(r[30]), "=r"(r[31])
                    : "r"(tb + j * 32));
                asm volatile("tcgen05.wait::ld.sync.aligned;" ::: "memory");

                const unsigned o4 = ob + j * 4;
                const float4 cr4 = *reinterpret_cast<const float4*>(cxp + o4);
                const float4 ci4 = *reinterpret_cast<const float4*>(cxp + 1024 + o4);
                float htr[4], hti[4], ctr[4], cti[4];
#pragma unroll
                for (int q = 0; q < 4; q++) {
                    const int c0 = q * 8;
                    const float* sbp = sbias + b * 256 + j * 32 + c0;
                    cell_math(
                        __uint_as_float(r[c0 + 0]) + sbp[0], __uint_as_float(r[c0 + 1]) + sbp[1],
                        __uint_as_float(r[c0 + 2]) + sbp[2], __uint_as_float(r[c0 + 3]) + sbp[3],
                        __uint_as_float(r[c0 + 4]) + sbp[4], __uint_as_float(r[c0 + 5]) + sbp[5],
                        __uint_as_float(r[c0 + 6]) + sbp[6], __uint_as_float(r[c0 + 7]) + sbp[7],
                        (&cr4.x)[q], (&ci4.x)[q],
                        htr[q], hti[q], ctr[q], cti[q]);
                }
                *reinterpret_cast<float4*>(out + hrow + o4) =
                    make_float4(htr[0], htr[1], htr[2], htr[3]);
                *reinterpret_cast<float4*>(out + hrow + 1024 + o4) =
                    make_float4(hti[0], hti[1], hti[2], hti[3]);
                *reinterpret_cast<float4*>(out + coff + hrow + o4) =
                    make_float4(ctr[0], ctr[1], ctr[2], ctr[3]);
                *reinterpret_cast<float4*>(out + coff + hrow + 1024 + o4) =
                    make_float4(cti[0], cti[1], cti[2], cti[3]);
            }
            asm volatile("tcgen05.fence::before_thread_sync;" ::: "memory");
            asm volatile("bar.sync 1, 128;" ::: "memory");
            if (tid == 0) {
                asm volatile("{\n\t.reg .b32 rem;\n\t"
                    "mapa.shared::cluster.u32 rem, %0, 0;\n\t"
                    "mbarrier.arrive.release.cluster.shared::cluster.b64 _, [rem];\n\t}"
                    :: "r"(accfB + b * 8) : "memory");
            }
        }
    } else if (tid == 128) {
        // ============ TMA issuer (both CTAs), 6 loads per chunk ============
        unsigned ci = 0;
        for (unsigned ti = 0; ti < ntiles; ti++) {
            const unsigned tile = ti * NCLUST + cid;
            const unsigned m0 = (tile >> 5) * 256;
            const unsigned n0 = (tile & 31) * 256;
            const int yA  = (int)(m0 + rank * 128);
            const int yB0 = (int)(n0 + rank * 64);
            const int yB1 = (int)(n0 + 128 + rank * 64);
            for (int i = 0; i < NCHUNK; i++, ci++) {
                const unsigned s = ci % NSTAGE, w = ci / NSTAGE;
                if (w >= 1) MBAR_WAIT_RLX(empB + s * 8, (w - 1) & 1);  // async-proxy only after
                const unsigned sb = tiles + s * STAGE_BYTES;
                const int k0 = i * KCH;
                const unsigned mb = xfB + s * 8;
                TMA2D_CG2(sb + A_H,        &tmAh, k0, yA,  mb);
                TMA2D_CG2(sb + A_L,        &tmAl, k0, yA,  mb);
                TMA2D_CG2(sb + B_H,        &tmBh, k0, yB0, mb);
                TMA2D_CG2(sb + B_H + 8192, &tmBh, k0, yB1, mb);
                TMA2D_CG2(sb + B_L,        &tmBl, k0, yB0, mb);
                TMA2D_CG2(sb + B_L + 8192, &tmBl, k0, yB1, mb);
            }
        }
    } else if (tid == 192 && rank == 0) {
        // ============ MMA issue thread (leader only) ============
        const unsigned long long DBASE =
            (2ull << 61) | (1ull << 46) | (64ull << 32) | (1ull << 16);
        unsigned ci = 0;
        for (unsigned ti = 0; ti < ntiles; ti++) {
            const unsigned b = ti & 1;
            if (ti >= 2) MBAR_WAIT_CL(accfB + b * 8, ((ti - 2) >> 1) & 1);
            const unsigned dbase = tmem + b * 256;
            for (int i = 0; i < NCHUNK; i++, ci++) {
                const unsigned s = ci % NSTAGE, w = ci / NSTAGE;
                MBAR_WAIT_CL_RLX(xfB + s * 8, w & 1);    // async-proxy only after
                MBAR_EXPECT_TX(xfB + s * 8, CHUNK_TX);   // arm next round
                const unsigned sb = tiles + s * STAGE_BYTES;
                const unsigned long long ah = DBASE | ((unsigned long long)((sb + A_H) >> 4) & 0x3FFF);
                const unsigned long long al = DBASE | ((unsigned long long)((sb + A_L) >> 4) & 0x3FFF);
                const unsigned long long bh = DBASE | ((unsigned long long)((sb + B_H) >> 4) & 0x3FFF);
                const unsigned long long bl = DBASE | ((unsigned long long)((sb + B_L) >> 4) & 0x3FFF);
#pragma unroll
                for (int half = 0; half < 2; half++) {
                    const unsigned d = dbase + half * 128;
                    const unsigned long long bo = (unsigned long long)half * 512;
#pragma unroll
                    for (int ks = 0; ks < 4; ks++)
                        MMA_CG2(d, ah + ks * 2, bh + bo + ks * 2,
                                (i == 0 && ks == 0) ? 0u : 1u);
#pragma unroll
                    for (int ks = 0; ks < 4; ks++)
                        MMA_CG2(d, ah + ks * 2, bl + bo + ks * 2, 1u);
#pragma unroll
                    for (int ks = 0; ks < 4; ks++)
                        MMA_CG2(d, al + ks * 2, bh + bo + ks * 2, 1u);
                }
                asm volatile("tcgen05.commit.cta_group::2.mbarrier::arrive::one"
                    ".shared::cluster.multicast::cluster.b64 [%0], %1;"
                    :: "r"(empB + s * 8), "h"((unsigned short)0x3) : "memory");
            }
            asm volatile("tcgen05.commit.cta_group::2.mbarrier::arrive::one"
                ".shared::cluster.multicast::cluster.b64 [%0], %1;"
                :: "r"(accdB + b * 8), "h"((unsigned short)0x3) : "memory");
        }
    }
    __syncthreads();
    if ((tid >> 5) == 4) {
        asm volatile("tcgen05.relinquish_alloc_permit.cta_group::2.sync.aligned;");
        asm volatile("tcgen05.dealloc.cta_group::2.sync.aligned.b32 %0, %1;"
            :: "r"(tmem), "r"(512u));
    }
    CLUSTER_SYNC_();

#else
    // ======== HMMA fallback (plain sm_103; never selected on GB300) ========
    #define HKC 32
    #define HNCH (KTOT / HKC)
    #define HSTG 40960
    #define HA_H 0
    #define HA_L 10240
    #define HB_H 20480
    #define HB_L 30720
    #define RST 80

    const int lane = tid & 31;
    const int w = tid >> 5;
    const unsigned base = smem_to_u32(dsm);
    const unsigned m_base = (unsigned)(w & 1) * 64;
    const unsigned n_base = (unsigned)(w >> 1) * 32;

    #define LDSM_X4(r0, r1, r2, r3, addr) \
        asm volatile("ldmatrix.sync.aligned.m8n8.x4.shared.b16 {%0,%1,%2,%3}, [%4];" \
            : "=r"(r0), "=r"(r1), "=r"(r2), "=r"(r3) : "r"(addr))
    #define LDSM_X2(r0, r1, addr) \
        asm volatile("ldmatrix.sync.aligned.m8n8.x2.shared.b16 {%0,%1}, [%2];" \
            : "=r"(r0), "=r"(r1) : "r"(addr))
    #define MMA_BF16(ac, av, bv) \
        asm volatile("mma.sync.aligned.m16n8k16.row.col.f32.bf16.bf16.f32 " \
            "{%0,%1,%2,%3}, {%4,%5,%6,%7}, {%8,%9}, {%0,%1,%2,%3};" \
            : "+f"((ac)[0]), "+f"((ac)[1]), "+f"((ac)[2]), "+f"((ac)[3]) \
            : "r"((av)[0]), "r"((av)[1]), "r"((av)[2]), "r"((av)[3]), \
              "r"((bv)[0]), "r"((bv)[1]))

    for (unsigned ti = 0; ti < ntiles; ti++) {
        const unsigned tile = ti * NCLUST + cid;
        const unsigned m0 = (tile >> 5) * 256;
        const unsigned n0 = (tile & 31) * 256;
        const unsigned fm0 = m0 + rank * 128;

        for (int nh = 0; nh < 2; nh++) {
            const unsigned n0h = n0 + nh * 128;
            float acc[4][4][4];
#pragma unroll
            for (int a = 0; a < 4; a++)
#pragma unroll
                for (int bq = 0; bq < 4; bq++)
#pragma unroll
                    for (int c = 0; c < 4; c++) acc[a][bq][c] = 0.0f;

            auto load_stage = [&](unsigned sb, unsigned k0) {
                for (unsigned idx = (unsigned)tid; idx < 2048; idx += 256) {
                    const unsigned mat = idx >> 9;
                    const unsigned rem = idx & 511;
                    const unsigned row = rem >> 2;
                    const unsigned c = rem & 3;
                    const __nv_bfloat16* src;
                    if (mat == 0)      src = g_Ah + (size_t)(fm0 + row) * KTOT + k0 + c * 8;
                    else if (mat == 1) src = g_Al + (size_t)(fm0 + row) * KTOT + k0 + c * 8;
                    else if (mat == 2) src = g_Bh + (size_t)(n0h + row) * KTOT + k0 + c * 8;
                    else               src = g_Bl + (size_t)(n0h + row) * KTOT + k0 + c * 8;
                    cp_async16(sb + mat * 10240 + row * RST + c * 16, src);
                }
            };

            load_stage(base + 0 * HSTG, 0);   CP_COMMIT();
            load_stage(base + 1 * HSTG, HKC); CP_COMMIT();

            for (int i = 0; i < HNCH; i++) {
                CP_WAIT1();
                __syncthreads();
                if (i + 2 < HNCH) load_stage(base + (unsigned)((i + 2) % 3) * HSTG, (i + 2) * HKC);
                CP_COMMIT();

                const unsigned sb = base + (unsigned)(i % 3) * HSTG;
#pragma unroll
                for (int ks = 0; ks < 2; ks++) {
                    unsigned a[4][4], bhv[4][2], blv[4][2];
                    const unsigned acol = (unsigned)(ks * 2 + (lane >> 4)) * 16;
                    const unsigned bcol = (unsigned)(ks * 2 + ((lane >> 3) & 1)) * 16;
#pragma unroll
                    for (int mt = 0; mt < 4; mt++) {
                        const unsigned ad = sb + HA_H
                            + (m_base + mt * 16 + (lane & 15)) * RST + acol;
                        LDSM_X4(a[mt][0], a[mt][1], a[mt][2], a[mt][3], ad);
                    }
#pragma unroll
                    for (int nt = 0; nt < 4; nt++) {
                        const unsigned brow = (n_base + nt * 8 + (lane & 7)) * RST + bcol;
                        LDSM_X2(bhv[nt][0], bhv[nt][1], sb + HB_H + brow);
                        LDSM_X2(blv[nt][0], blv[nt][1], sb + HB_L + brow);
                    }
#pragma unroll
                    for (int mt = 0; mt < 4; mt++)
#pragma unroll
                        for (int nt = 0; nt < 4; nt++) {
                            MMA_BF16(acc[mt][nt], a[mt], bhv[nt]);
                            MMA_BF16(acc[mt][nt], a[mt], blv[nt]);
                        }
#pragma unroll
                    for (int mt = 0; mt < 4; mt++) {
                        const unsigned ad = sb + HA_L
                            + (m_base + mt * 16 + (lane & 15)) * RST + acol;
                        LDSM_X4(a[mt][0], a[mt][1], a[mt][2], a[mt][3], ad);
                    }
#pragma unroll
                    for (int mt = 0; mt < 4; mt++)
#pragma unroll
                        for (int nt = 0; nt < 4; nt++)
                            MMA_BF16(acc[mt][nt], a[mt], bhv[nt]);
                }
                __syncthreads();
            }

#pragma unroll
            for (int mt = 0; mt < 4; mt++) {
                const unsigned row0 = fm0 + m_base + mt * 16 + (lane >> 2);
#pragma unroll
                for (int nt = 0; nt < 4; nt++) {
                    const unsigned col = n0h + n_base + nt * 8 + 2 * (lane & 3);
                    *reinterpret_cast<float2*>(&g_z[(size_t)row0 * NTOT + col]) =
                        make_float2(acc[mt][nt][0], acc[mt][nt][1]);
                    *reinterpret_cast<float2*>(&g_z[(size_t)(row0 + 8) * NTOT + col]) =
                        make_float2(acc[mt][nt][2], acc[mt][nt][3]);
                }
            }
            __syncthreads();
        }

        for (int e = tid; e < 128 * 32; e += 256) {
            const unsigned rr = e >> 5, oq = e & 31;
            const unsigned m = fm0 + rr;
            const unsigned o = (n0 >> 3) + oq;
            const float* zp = g_z + (size_t)m * NTOT + n0 + oq * 8;
            const float* bp = g_biasC + n0 + oq * 8;
            const float cr = c_x[(size_t)m * 2048 + o];
            const float ci = c_x[(size_t)m * 2048 + 1024 + o];
            float htr, hti, ctr, cti;
            cell_math(zp[0] + bp[0], zp[1] + bp[1], zp[2] + bp[2], zp[3] + bp[3],
                      zp[4] + bp[4], zp[5] + bp[5], zp[6] + bp[6], zp[7] + bp[7],
                      cr, ci, htr, hti, ctr, cti);
            const size_t hrow = (size_t)m * 2048;
            const size_t coff = (size_t)BDIM * 2048;
            out[hrow + o] = htr;
            out[hrow + 1024 + o] = hti;
            out[coff + hrow + o] = ctr;
            out[coff + hrow + 1024 + o] = cti;
        }
        __syncthreads();
    }
#endif
}

// ---------------- merged prep kernel ----------------
__device__ __forceinline__ void split_bf16(float v, __nv_bfloat16& hi, __nv_bfloat16& lo) {
    hi = __float2bfloat16_rn(v);
    lo = __float2bfloat16_rn(v - __bfloat162float(hi));
}

#define ACT_BLKS 16384
#define W_BLKS 32768

__global__ __launch_bounds__(256)
void prep_all_kernel(const float* __restrict__ input, const float* __restrict__ h_x,
                     const float* __restrict__ Uw_r, const float* __restrict__ Uw_i,
                     const float* __restrict__ Ww_r, const float* __restrict__ Ww_i,
                     const float* __restrict__ Ub_r, const float* __restrict__ Ub_i,
                     const float* __restrict__ Wb_r, const float* __restrict__ Wb_i) {
    const unsigned bid = blockIdx.x;
    if (bid < ACT_BLKS) {
        const unsigned idx = bid * 256 + threadIdx.x;
        const unsigned m = idx >> 10;
        const unsigned k = (idx & 1023) * 4;
        const float* src = (k < 2048) ? (input + (size_t)m * 2048 + k)
                                      : (h_x   + (size_t)m * 2048 + (k - 2048));
        float4 v = *reinterpret_cast<const float4*>(src);
        union { __nv_bfloat16 b[4]; uint2 u; } ph, pl;
        split_bf16(v.x, ph.b[0], pl.b[0]);
        split_bf16(v.y, ph.b[1], pl.b[1]);
        split_bf16(v.z, ph.b[2], pl.b[2]);
        split_bf16(v.w, ph.b[3], pl.b[3]);
        const size_t off = (size_t)m * KTOT + k;
        *reinterpret_cast<uint2*>(&g_Ah[off]) = ph.u;
        *reinterpret_cast<uint2*>(&g_Al[off]) = pl.u;
    } else if (bid < ACT_BLKS + W_BLKS) {
        const unsigned idx = (bid - ACT_BLKS) * 256 + threadIdx.x;
        const unsigned n = idx >> 10;              // n' (interleaved)
        const unsigned k = (idx & 1023) * 4;
        const unsigned o  = n >> 3;
        const unsigned g  = (n >> 1) & 3;
        const unsigned ri = n & 1;
        const unsigned seg = k >> 10, kk = k & 1023;

        const float* src;
        float s;
        if (ri == 0) {
            switch (seg) {
                case 0: src = Uw_r; s =  1.0f; break;
                case 1: src = Uw_i; s = -1.0f; break;
                case 2: src = Ww_r; s =  1.0f; break;
                default: src = Ww_i; s = -1.0f; break;
            }
        } else {
            switch (seg) {
                case 0: src = Uw_i; s = 1.0f; break;
                case 1: src = Uw_r; s = 1.0f; break;
                case 2: src = Ww_i; s = 1.0f; break;
                default: src = Ww_r; s = 1.0f; break;
            }
        }
        float4 v = *reinterpret_cast<const float4*>(src + ((size_t)(g * 1024 + o)) * 1024 + kk);
        union { __nv_bfloat16 b[4]; uint2 u; } ph, pl;
        split_bf16(s * v.x, ph.b[0], pl.b[0]);
        split_bf16(s * v.y, ph.b[1], pl.b[1]);
        split_bf16(s * v.z, ph.b[2], pl.b[2]);
        split_bf16(s * v.w, ph.b[3], pl.b[3]);
        const size_t off = (size_t)n * KTOT + k;
        *reinterpret_cast<uint2*>(&g_Bh[off]) = ph.u;
        *reinterpret_cast<uint2*>(&g_Bl[off]) = pl.u;
    } else {
        const unsigned n = (bid - ACT_BLKS - W_BLKS) * 256 + threadIdx.x;
        const unsigned o  = n >> 3;
        const unsigned g  = (n >> 1) & 3;
        const unsigned ri = n & 1;
        const unsigned go = g * 1024 + o;
        g_biasC[n] = ri ? (Ub_i[go] + Wb_i[go]) : (Ub_r[go] + Wb_r[go]);
    }
}

// ---------------- host ----------------
typedef CUresult (*EncodeTiledFn)(
    CUtensorMap*, CUtensorMapDataType, cuuint32_t, void*,
    const cuuint64_t*, const cuuint64_t*, const cuuint32_t*, const cuuint32_t*,
    CUtensorMapInterleave, CUtensorMapSwizzle, CUtensorMapL2promotion,
    CUtensorMapFloatOOBfill);

static void make_map(EncodeTiledFn enc, CUtensorMap* tm, void* ptr,
                     unsigned rows, unsigned box_rows) {
    cuuint64_t dims[2]    = {(cuuint64_t)KTOT, (cuuint64_t)rows};
    cuuint64_t strides[1] = {(cuuint64_t)KTOT * 2};
    cuuint32_t box[2]     = {64u, box_rows};       // 64 bf16 = 128B (SW128)
    cuuint32_t es[2]      = {1u, 1u};
    enc(tm, CU_TENSOR_MAP_DATA_TYPE_BFLOAT16, 2, ptr,
        dims, strides, box, es,
        CU_TENSOR_MAP_INTERLEAVE_NONE, CU_TENSOR_MAP_SWIZZLE_128B,
        CU_TENSOR_MAP_L2_PROMOTION_L2_128B, CU_TENSOR_MAP_FLOAT_OOB_FILL_NONE);
}

extern "C" void kernel_launch(void* const* d_in, const int* in_sizes, int n_in,
                              void* d_out, int out_size)
{
    const float* input = (const float*)d_in[0];
    const float* h_x   = (const float*)d_in[1];
    const float* c_x   = (const float*)d_in[2];
    const float* Uw_r  = (const float*)d_in[3];
    const float* Uw_i  = (const float*)d_in[4];
    const float* Ub_r  = (const float*)d_in[5];
    const float* Ub_i  = (const float*)d_in[6];
    const float* Ww_r  = (const float*)d_in[7];
    const float* Ww_i  = (const float*)d_in[8];
    const float* Wb_r  = (const float*)d_in[9];
    const float* Wb_i  = (const float*)d_in[10];
    float* out = (float*)d_out;

    // tensormaps (host-built each call; capture-time only)
    void* fnp = nullptr;
    cudaDriverEntryPointQueryResult qr;
    cudaGetDriverEntryPointByVersion("cuTensorMapEncodeTiled", &fnp, 12000,
                                     cudaEnableDefault, &qr);
    EncodeTiledFn enc = (EncodeTiledFn)fnp;

    void *pAh, *pAl, *pBh, *pBl;
    cudaGetSymbolAddress(&pAh, g_Ah);
    cudaGetSymbolAddress(&pAl, g_Al);
    cudaGetSymbolAddress(&pBh, g_Bh);
    cudaGetSymbolAddress(&pBl, g_Bl);

    CUtensorMap tmAh, tmAl, tmBh, tmBl;
    make_map(enc, &tmAh, pAh, BDIM, 128);
    make_map(enc, &tmAl, pAl, BDIM, 128);
    make_map(enc, &tmBh, pBh, NTOT, 64);
    make_map(enc, &tmBl, pBl, NTOT, 64);

    cudaFuncSetAttribute(clstm_tc_gemm_kernel,
                         cudaFuncAttributeMaxDynamicSharedMemorySize, SMEM_BYTES);

    prep_all_kernel<<<ACT_BLKS + W_BLKS + NTOT / 256, 256>>>(
        input, h_x, Uw_r, Uw_i, Ww_r, Ww_i, Ub_r, Ub_i, Wb_r, Wb_i);

    dim3 grid(2 * NCLUST, 1, 1);   // 74 persistent 2-CTA clusters
    clstm_tc_gemm_kernel<<<grid, 256, SMEM_BYTES>>>(c_x, out, tmAh, tmAl, tmBh, tmBl);
}